// round 9
// baseline (speedup 1.0000x reference)
#include <cuda_runtime.h>
#include <math.h>

#define EPSF 1e-10f
#define NPAD 1024
typedef unsigned long long ull;

// ---------------- scratch (device globals; no allocation allowed) ----------------
// gathered points, channel-major: [level][b][ch][n], n padded to 1024 with zeros
__device__ float g_X[7864320];   // sum_l 8*c_l*1024
__device__ float g_Y[7864320];
__device__ float g_XT[7864320];  // transposed: [level][b][n][ch]
__device__ float g_YT[7864320];
__device__ float g_normX[4 * 8 * 1024];
__device__ float g_normY[4 * 8 * 1024];
__device__ float g_meanX[4 * 8 * 512];
__device__ float g_meanY[4 * 8 * 512];
__device__ unsigned g_rowmin[4 * 8 * 1024];
__device__ unsigned g_colmin[4 * 8 * 1024];
__device__ float g_cxs[8 * 512 * 512];   // covX tile scratch, pitch 512, per batch
__device__ float g_covabs[32];   // [l*8+b]  sum |covX-covY|
__device__ float g_sm[32];       // [l*8+b]  style + mean-diff term

// ---------------- f32x2 helpers (SASS FFMA2 — PTX-only path) ----------------
__device__ __forceinline__ ull pack_dup(float x) {
    ull r; asm("mov.b64 %0, {%1, %1};" : "=l"(r) : "f"(x)); return r;
}
__device__ __forceinline__ void ffma2(ull& d, ull a, ull b) {
    asm("fma.rn.f32x2 %0, %1, %2, %0;" : "+l"(d) : "l"(a), "l"(b));
}
__device__ __forceinline__ float2 unpk(ull v) {
    float2 f; asm("mov.b64 {%0, %1}, %2;" : "=f"(f.x), "=f"(f.y) : "l"(v)); return f;
}

// ---------------- init ----------------
__global__ void init_kernel() {
    int t = blockIdx.x * 256 + threadIdx.x;
    if (t < 4 * 8 * 1024) {
        g_rowmin[t] = 0x7F7FFFFFu;   // FLT_MAX bits; distances > 0 so uint order == float order
        g_colmin[t] = 0x7F7FFFFFu;
    }
    if (t < 32) g_covabs[t] = 0.f;
}

// ---------------- gather: feat (B,c,h,w) + idx -> X[ch][1024] zero-padded ----------------
__global__ void gather_kernel(const float* __restrict__ tgt, const float* __restrict__ gen,
                              const int* __restrict__ idx, int c, int hw, int N, int off) {
    int b = blockIdx.y, tsel = blockIdx.z;
    const float* src = tsel ? gen : tgt;
    float* dst = (tsel ? g_Y : g_X) + off;
    int t = blockIdx.x * 256 + threadIdx.x;     // grid.x = c*4 so t < c*1024 always
    int ch = t >> 10, n = t & 1023;
    float v = 0.f;
    if (n < N) {
        int pos = idx ? idx[b * N + n] : n;
        v = src[((size_t)b * c + ch) * hw + pos];
    }
    dst[((size_t)b * c + ch) * NPAD + n] = v;   // coalesced over n
}

// ---------------- transpose: [ch][n] -> [n][ch] (for cov passes) ----------------
__global__ void transpose_kernel(int c, int off) {
    __shared__ float tile[32][33];
    int b = blockIdx.z & 7, tsel = blockIdx.z >> 3;
    const float* src = (tsel ? g_Y : g_X) + off + (size_t)b * c * NPAD;
    float* dst = (tsel ? g_YT : g_XT) + off + (size_t)b * c * NPAD;
    int ch0 = blockIdx.x * 32, n0 = blockIdx.y * 32;
#pragma unroll
    for (int r = threadIdx.y; r < 32; r += 8)
        tile[r][threadIdx.x] = src[(size_t)(ch0 + r) * NPAD + n0 + threadIdx.x];
    __syncthreads();
#pragma unroll
    for (int r = threadIdx.y; r < 32; r += 8)
        dst[(size_t)(n0 + r) * c + ch0 + threadIdx.x] = tile[threadIdx.x][r];
}

// ---------------- per-point L2 norms ----------------
__global__ void norms_kernel(int c, int off, int lvl) {
    int b = blockIdx.y, tsel = blockIdx.z;
    const float* src = (tsel ? g_Y : g_X) + off + (size_t)b * c * NPAD;
    float* dst = (tsel ? g_normY : g_normX) + (lvl * 8 + b) * 1024;
    int n = blockIdx.x * 256 + threadIdx.x;
    float s = 0.f;
    for (int ch = 0; ch < c; ch++) { float v = src[ch * NPAD + n]; s += v * v; }
    dst[n] = sqrtf(s);
}

// ---------------- per-channel means (warp per channel) ----------------
__global__ void means_kernel(int c, int N, int off, int lvl) {
    int b = blockIdx.y, tsel = blockIdx.z;
    const float* src = (tsel ? g_Y : g_X) + off + (size_t)b * c * NPAD;
    float* dst = (tsel ? g_meanY : g_meanX) + (lvl * 8 + b) * 512;
    int ch = blockIdx.x * 8 + (threadIdx.x >> 5);
    int lane = threadIdx.x & 31;
    if (ch >= c) return;
    float s = 0.f;
    for (int n = lane; n < NPAD; n += 32) s += src[ch * NPAD + n];
#pragma unroll
    for (int o = 16; o; o >>= 1) s += __shfl_xor_sync(0xFFFFFFFFu, s, o);
    if (lane == 0) dst[ch] = s / (float)N;
}

// ---------------- Gram + cosine distance + row/col min (128x128 tile, 8x8 FFMA2) ----------------
__global__ void __launch_bounds__(256, 2) gram_kernel(int c, int N, int off, int lvl) {
    int b = blockIdx.z;
    const float* __restrict__ Xb = g_X + off + (size_t)b * c * NPAD;
    const float* __restrict__ Yb = g_Y + off + (size_t)b * c * NPAD;
    int i0 = blockIdx.y * 128, j0 = blockIdx.x * 128;
    __shared__ float As[16][128], Bs[16][128];
    int tx = threadIdx.x & 15, ty = threadIdx.x >> 4;
    ull acc[8][4];
#pragma unroll
    for (int i = 0; i < 8; i++)
#pragma unroll
        for (int j = 0; j < 4; j++) acc[i][j] = 0ull;

    for (int k0 = 0; k0 < c; k0 += 16) {
#pragma unroll
        for (int r = 0; r < 2; r++) {
            int id = r * 256 + threadIdx.x;
            int kk = id >> 5, nn = (id & 31) * 4;
            *(float4*)&As[kk][nn] = *(const float4*)&Xb[(size_t)(k0 + kk) * NPAD + i0 + nn];
            *(float4*)&Bs[kk][nn] = *(const float4*)&Yb[(size_t)(k0 + kk) * NPAD + j0 + nn];
        }
        __syncthreads();
#pragma unroll
        for (int k = 0; k < 16; k++) {
            ulonglong2 pb01 = *(const ulonglong2*)&Bs[k][tx * 8];
            ulonglong2 pb23 = *(const ulonglong2*)&Bs[k][tx * 8 + 4];
            float4 a0_ = *(const float4*)&As[k][ty * 8];
            float4 a1_ = *(const float4*)&As[k][ty * 8 + 4];
            float av[8] = {a0_.x, a0_.y, a0_.z, a0_.w, a1_.x, a1_.y, a1_.z, a1_.w};
#pragma unroll
            for (int i = 0; i < 8; i++) {
                ull pa = pack_dup(av[i]);
                ffma2(acc[i][0], pa, pb01.x);
                ffma2(acc[i][1], pa, pb01.y);
                ffma2(acc[i][2], pa, pb23.x);
                ffma2(acc[i][3], pa, pb23.y);
            }
        }
        __syncthreads();
    }

    // epilogue: cosine distance + tile-local min reduction
    __shared__ unsigned srow[128], scol[128];
    if (threadIdx.x < 128) { srow[threadIdx.x] = 0x7F7FFFFFu; scol[threadIdx.x] = 0x7F7FFFFFu; }
    __syncthreads();
    const float* nX = g_normX + (lvl * 8 + b) * 1024;
    const float* nY = g_normY + (lvl * 8 + b) * 1024;
    float nx[8], ny[8];
#pragma unroll
    for (int i = 0; i < 8; i++) {
        nx[i] = nX[i0 + ty * 8 + i] + EPSF;
        ny[i] = nY[j0 + tx * 8 + i] + EPSF;
    }
    float colm[8];
#pragma unroll
    for (int j = 0; j < 8; j++) colm[j] = 3.402823466e+38f;
#pragma unroll
    for (int i = 0; i < 8; i++) {
        int gi = i0 + ty * 8 + i;
        bool iv = gi < N;
        float rowm = 3.402823466e+38f;
#pragma unroll
        for (int jp = 0; jp < 4; jp++) {
            float2 d2 = unpk(acc[i][jp]);
            int gj = j0 + tx * 8 + jp * 2;
            float d0 = 1.0f - d2.x / nx[i] / ny[jp * 2];       // matches ref's double division
            float d1 = 1.0f - d2.y / nx[i] / ny[jp * 2 + 1];
            if (gj < N)     { rowm = fminf(rowm, d0); if (iv) colm[jp * 2]     = fminf(colm[jp * 2], d0); }
            if (gj + 1 < N) { rowm = fminf(rowm, d1); if (iv) colm[jp * 2 + 1] = fminf(colm[jp * 2 + 1], d1); }
        }
        if (iv && rowm < 3.402823466e+38f) atomicMin(&srow[ty * 8 + i], __float_as_uint(rowm));
    }
#pragma unroll
    for (int j = 0; j < 8; j++)
        if (colm[j] < 3.402823466e+38f) atomicMin(&scol[tx * 8 + j], __float_as_uint(colm[j]));
    __syncthreads();
    if (threadIdx.x < 128) {
        int gi = i0 + threadIdx.x, gj = j0 + threadIdx.x;
        if (gi < N) atomicMin(&g_rowmin[(lvl * 8 + b) * 1024 + gi], srow[threadIdx.x]);
        if (gj < N) atomicMin(&g_colmin[(lvl * 8 + b) * 1024 + gj], scol[threadIdx.x]);
    }
}

// ---------------- covariance pass: gram-shaped GEMM over transposed data ----------------
// pass 0: cov tile from XT -> g_cxs.  pass 1: cov tile from YT, accumulate w*|cx-cy|.
__global__ void __launch_bounds__(256, 2) covpass_kernel(int c, int N, int off, int lvl, int pass) {
    int a0 = blockIdx.y * 128, b0 = blockIdx.x * 128;
    if (a0 > b0) return;                         // upper-triangle tiles only
    int b = blockIdx.z;
    const float* __restrict__ T = (pass ? g_YT : g_XT) + off + (size_t)b * c * NPAD;
    const float* __restrict__ mu = (pass ? g_meanY : g_meanX) + (lvl * 8 + b) * 512;
    float* cxs = g_cxs + (size_t)b * 262144;     // pitch 512
    __shared__ float As[16][128], Bs[16][128];
    int tx = threadIdx.x & 15, ty = threadIdx.x >> 4;
    ull acc[8][4];
#pragma unroll
    for (int i = 0; i < 8; i++)
#pragma unroll
        for (int j = 0; j < 4; j++) acc[i][j] = 0ull;

    for (int k0 = 0; k0 < NPAD; k0 += 16) {
#pragma unroll
        for (int r = 0; r < 2; r++) {
            int id = r * 256 + threadIdx.x;
            int kk = id >> 5, nn = (id & 31) * 4;
            *(float4*)&As[kk][nn] = *(const float4*)&T[(size_t)(k0 + kk) * c + a0 + nn];
            *(float4*)&Bs[kk][nn] = *(const float4*)&T[(size_t)(k0 + kk) * c + b0 + nn];
        }
        __syncthreads();
#pragma unroll
        for (int k = 0; k < 16; k++) {
            ulonglong2 pb01 = *(const ulonglong2*)&Bs[k][tx * 8];
            ulonglong2 pb23 = *(const ulonglong2*)&Bs[k][tx * 8 + 4];
            float4 a0_ = *(const float4*)&As[k][ty * 8];
            float4 a1_ = *(const float4*)&As[k][ty * 8 + 4];
            float av[8] = {a0_.x, a0_.y, a0_.z, a0_.w, a1_.x, a1_.y, a1_.z, a1_.w};
#pragma unroll
            for (int i = 0; i < 8; i++) {
                ull pa = pack_dup(av[i]);
                ffma2(acc[i][0], pa, pb01.x);
                ffma2(acc[i][1], pa, pb01.y);
                ffma2(acc[i][2], pa, pb23.x);
                ffma2(acc[i][3], pa, pb23.y);
            }
        }
        __syncthreads();
    }

    float inv = 1.0f / (float)(N - 1), fN = (float)N;
    float ma[8], mb[8];
#pragma unroll
    for (int i = 0; i < 8; i++) { ma[i] = mu[a0 + ty * 8 + i]; mb[i] = mu[b0 + tx * 8 + i]; }

    if (pass == 0) {
#pragma unroll
        for (int i = 0; i < 8; i++) {
            int ga = a0 + ty * 8 + i;
            float* row = cxs + (size_t)ga * 512 + b0 + tx * 8;
#pragma unroll
            for (int jp = 0; jp < 4; jp++) {
                float2 d2 = unpk(acc[i][jp]);
                float2 cx;
                cx.x = (d2.x - fN * ma[i] * mb[jp * 2])     * inv;
                cx.y = (d2.y - fN * ma[i] * mb[jp * 2 + 1]) * inv;
                *(float2*)&row[jp * 2] = cx;
            }
        }
    } else {
        float local = 0.f;
#pragma unroll
        for (int i = 0; i < 8; i++) {
            int ga = a0 + ty * 8 + i;
            const float* row = cxs + (size_t)ga * 512 + b0 + tx * 8;
#pragma unroll
            for (int jp = 0; jp < 4; jp++) {
                float2 d2 = unpk(acc[i][jp]);
                int gb = b0 + tx * 8 + jp * 2;
                float cy0 = (d2.x - fN * ma[i] * mb[jp * 2])     * inv;
                float cy1 = (d2.y - fN * ma[i] * mb[jp * 2 + 1]) * inv;
                float2 cx = *(const float2*)&row[jp * 2];
                if (ga < c && gb < c && ga <= gb)
                    local += (ga < gb ? 2.f : 1.f) * fabsf(cx.x - cy0);
                if (ga < c && gb + 1 < c && ga <= gb + 1)
                    local += (ga < gb + 1 ? 2.f : 1.f) * fabsf(cx.y - cy1);
            }
        }
#pragma unroll
        for (int o = 16; o; o >>= 1) local += __shfl_xor_sync(0xFFFFFFFFu, local, o);
        __shared__ float red[8];
        if ((threadIdx.x & 31) == 0) red[threadIdx.x >> 5] = local;
        __syncthreads();
        if (threadIdx.x == 0) {
            float s = 0.f;
            for (int i = 0; i < 8; i++) s += red[i];
            atomicAdd(&g_covabs[lvl * 8 + b], s);
        }
    }
}

// ---------------- style (max of mean-mins) + mean-abs-diff term, per (b, level) ----------------
__global__ void stylered_kernel() {
    int b = blockIdx.x, l = blockIdx.y;
    const int cs_[4] = {64, 128, 256, 512};
    const int Ns_[4] = {1000, 1000, 1000, 1024};
    int c = cs_[l], N = Ns_[l];
    int base = (l * 8 + b) * 1024;
    float rs = 0.f, csu = 0.f;
    for (int i = threadIdx.x; i < N; i += 256) {
        rs  += __uint_as_float(g_rowmin[base + i]);
        csu += __uint_as_float(g_colmin[base + i]);
    }
    int mbase = (l * 8 + b) * 512;
    float ms = 0.f;
    for (int ch = threadIdx.x; ch < c; ch += 256)
        ms += fabsf(g_meanX[mbase + ch] - g_meanY[mbase + ch]);

    __shared__ float s1[256], s2[256], s3[256];
    int t = threadIdx.x;
    s1[t] = rs; s2[t] = csu; s3[t] = ms;
    __syncthreads();
    for (int o = 128; o; o >>= 1) {
        if (t < o) { s1[t] += s1[t + o]; s2[t] += s2[t + o]; s3[t] += s3[t + o]; }
        __syncthreads();
    }
    if (t == 0) {
        float style = fmaxf(s1[0] / (float)N, s2[0] / (float)N);
        g_sm[l * 8 + b] = style + s3[0] / (float)c;
    }
}

// ---------------- final scalar ----------------
__global__ void final_kernel(float* __restrict__ out) {
    int t = threadIdx.x;   // 32 threads = 4 levels * 8 batches
    const int cs_[4] = {64, 128, 256, 512};
    int l = t >> 3;
    float cc = (float)cs_[l];
    float v = g_sm[t] + g_covabs[t] / (cc * cc);
#pragma unroll
    for (int o = 16; o; o >>= 1) v += __shfl_xor_sync(0xFFFFFFFFu, v, o);
    if (t == 0) out[0] = v * 0.125f;   // mean over batch
}

// ---------------- host launcher ----------------
extern "C" void kernel_launch(void* const* d_in, const int* in_sizes, int n_in,
                              void* d_out, int out_size) {
    (void)out_size;
    const float* tgt[4] = {nullptr, nullptr, nullptr, nullptr};
    const float* gen[4] = {nullptr, nullptr, nullptr, nullptr};
    const int* idxp[3]  = {nullptr, nullptr, nullptr};
    int ni = 0;
    for (int i = 0; i < n_in; i++) {
        int lvl = -1;
        switch (in_sizes[i]) {
            case 33554432: lvl = 0; break;   // 8*64*256*256
            case 16777216: lvl = 1; break;   // 8*128*128*128
            case 8388608:  lvl = 2; break;   // 8*256*64*64
            case 4194304:  lvl = 3; break;   // 8*512*32*32
            case 8000: if (ni < 3) idxp[ni++] = (const int*)d_in[i]; break;
            default: break;
        }
        if (lvl >= 0) {
            if (!tgt[lvl]) tgt[lvl] = (const float*)d_in[i];
            else           gen[lvl] = (const float*)d_in[i];
        }
    }

    const int cs[4]   = {64, 128, 256, 512};
    const int Ns[4]   = {1000, 1000, 1000, 1024};
    const int hws[4]  = {65536, 16384, 4096, 1024};
    const int offs[4] = {0, 524288, 1572864, 3670016};

    init_kernel<<<256, 256>>>();
    for (int l = 0; l < 4; l++)
        gather_kernel<<<dim3(cs[l] * 4, 8, 2), 256>>>(
            tgt[l], gen[l], (l < 3) ? idxp[l] : nullptr, cs[l], hws[l], Ns[l], offs[l]);
    for (int l = 0; l < 4; l++)
        transpose_kernel<<<dim3(cs[l] / 32, 32, 16), dim3(32, 8)>>>(cs[l], offs[l]);
    for (int l = 0; l < 4; l++) {
        norms_kernel<<<dim3(4, 8, 2), 256>>>(cs[l], offs[l], l);
        means_kernel<<<dim3(cs[l] / 8, 8, 2), 256>>>(cs[l], Ns[l], offs[l], l);
    }
    for (int l = 0; l < 4; l++)
        gram_kernel<<<dim3(8, 8, 8), 256>>>(cs[l], Ns[l], offs[l], l);
    for (int l = 0; l < 4; l++) {
        int gt = (cs[l] + 127) / 128;
        covpass_kernel<<<dim3(gt, gt, 8), 256>>>(cs[l], Ns[l], offs[l], l, 0);
        covpass_kernel<<<dim3(gt, gt, 8), 256>>>(cs[l], Ns[l], offs[l], l, 1);
    }
    stylered_kernel<<<dim3(8, 4), 256>>>();
    final_kernel<<<1, 32>>>((float*)d_out);
}

// round 10
// speedup vs baseline: 1.0615x; 1.0615x over previous
#include <cuda_runtime.h>
#include <math.h>

#define EPSF 1e-10f
#define NPAD 1024

// ---------------- scratch (device globals; no allocation allowed) ----------------
// gathered points, channel-major: [level][b][ch][n], n padded to 1024 with zeros
__device__ float g_X[7864320];   // sum_l 8*c_l*1024
__device__ float g_Y[7864320];
__device__ float g_XT[7864320];  // transposed: [level][b][n][ch]
__device__ float g_YT[7864320];
__device__ float g_normX[4 * 8 * 1024];
__device__ float g_normY[4 * 8 * 1024];
__device__ float g_meanX[4 * 8 * 512];
__device__ float g_meanY[4 * 8 * 512];
__device__ unsigned g_rowmin[4 * 8 * 1024];
__device__ unsigned g_colmin[4 * 8 * 1024];
__device__ float g_cxs[8 * 512 * 512];   // covX tile scratch, pitch 512, per batch
__device__ float g_covabs[32];   // [l*8+b]  sum |covX-covY|
__device__ float g_sm[32];       // [l*8+b]  style + mean-diff term

// ---------------- init ----------------
__global__ void init_kernel() {
    int t = blockIdx.x * 256 + threadIdx.x;
    if (t < 4 * 8 * 1024) {
        g_rowmin[t] = 0x7F7FFFFFu;   // FLT_MAX bits; distances > 0 so uint order == float order
        g_colmin[t] = 0x7F7FFFFFu;
    }
    if (t < 32) g_covabs[t] = 0.f;
}

// ---------------- gather: feat (B,c,h,w) + idx -> X[ch][1024] zero-padded ----------------
__global__ void gather_kernel(const float* __restrict__ tgt, const float* __restrict__ gen,
                              const int* __restrict__ idx, int c, int hw, int N, int off) {
    int b = blockIdx.y, tsel = blockIdx.z;
    const float* src = tsel ? gen : tgt;
    float* dst = (tsel ? g_Y : g_X) + off;
    int t = blockIdx.x * 256 + threadIdx.x;     // grid.x = c*4 so t < c*1024 always
    int ch = t >> 10, n = t & 1023;
    float v = 0.f;
    if (n < N) {
        int pos = idx ? idx[b * N + n] : n;
        v = src[((size_t)b * c + ch) * hw + pos];
    }
    dst[((size_t)b * c + ch) * NPAD + n] = v;   // coalesced over n
}

// ---------------- transpose: [ch][n] -> [n][ch] (for cov passes) ----------------
__global__ void transpose_kernel(int c, int off) {
    __shared__ float tile[32][33];
    int b = blockIdx.z & 7, tsel = blockIdx.z >> 3;
    const float* src = (tsel ? g_Y : g_X) + off + (size_t)b * c * NPAD;
    float* dst = (tsel ? g_YT : g_XT) + off + (size_t)b * c * NPAD;
    int ch0 = blockIdx.x * 32, n0 = blockIdx.y * 32;
#pragma unroll
    for (int r = threadIdx.y; r < 32; r += 8)
        tile[r][threadIdx.x] = src[(size_t)(ch0 + r) * NPAD + n0 + threadIdx.x];
    __syncthreads();
#pragma unroll
    for (int r = threadIdx.y; r < 32; r += 8)
        dst[(size_t)(n0 + r) * c + ch0 + threadIdx.x] = tile[threadIdx.x][r];
}

// ---------------- per-point L2 norms ----------------
__global__ void norms_kernel(int c, int off, int lvl) {
    int b = blockIdx.y, tsel = blockIdx.z;
    const float* src = (tsel ? g_Y : g_X) + off + (size_t)b * c * NPAD;
    float* dst = (tsel ? g_normY : g_normX) + (lvl * 8 + b) * 1024;
    int n = blockIdx.x * 256 + threadIdx.x;
    float s = 0.f;
    for (int ch = 0; ch < c; ch++) { float v = src[ch * NPAD + n]; s += v * v; }
    dst[n] = sqrtf(s);
}

// ---------------- per-channel means (warp per channel) ----------------
__global__ void means_kernel(int c, int N, int off, int lvl) {
    int b = blockIdx.y, tsel = blockIdx.z;
    const float* src = (tsel ? g_Y : g_X) + off + (size_t)b * c * NPAD;
    float* dst = (tsel ? g_meanY : g_meanX) + (lvl * 8 + b) * 512;
    int ch = blockIdx.x * 8 + (threadIdx.x >> 5);
    int lane = threadIdx.x & 31;
    if (ch >= c) return;
    float s = 0.f;
    for (int n = lane; n < NPAD; n += 32) s += src[ch * NPAD + n];
#pragma unroll
    for (int o = 16; o; o >>= 1) s += __shfl_xor_sync(0xFFFFFFFFu, s, o);
    if (lane == 0) dst[ch] = s / (float)N;
}

// column offset for the 8-wide microtile: two contiguous 64-float halves
__device__ __forceinline__ int colofs(int tx, int j) {
    return (j < 4) ? (tx * 4 + j) : (64 + tx * 4 + (j - 4));
}

// ---------------- Gram + cosine distance + row/col min (128x128 tile, 8x8 scalar FFMA) ----------------
__global__ void __launch_bounds__(256, 2) gram_kernel(int c, int N, int off, int lvl) {
    int b = blockIdx.z;
    const float* __restrict__ Xb = g_X + off + (size_t)b * c * NPAD;
    const float* __restrict__ Yb = g_Y + off + (size_t)b * c * NPAD;
    int i0 = blockIdx.y * 128, j0 = blockIdx.x * 128;
    __shared__ float As[16][128], Bs[16][128];
    int tx = threadIdx.x & 15, ty = threadIdx.x >> 4;
    float acc[8][8];
#pragma unroll
    for (int i = 0; i < 8; i++)
#pragma unroll
        for (int j = 0; j < 8; j++) acc[i][j] = 0.f;

    int kk = threadIdx.x >> 5;          // 0..7
    int nn = (threadIdx.x & 31) * 4;    // 0..124, float4 aligned

    // prefetch chunk 0
    float4 pa0 = *(const float4*)&Xb[(size_t)kk * NPAD + i0 + nn];
    float4 pa1 = *(const float4*)&Xb[(size_t)(kk + 8) * NPAD + i0 + nn];
    float4 pb0 = *(const float4*)&Yb[(size_t)kk * NPAD + j0 + nn];
    float4 pb1 = *(const float4*)&Yb[(size_t)(kk + 8) * NPAD + j0 + nn];

    for (int k0 = 0; k0 < c; k0 += 16) {
        *(float4*)&As[kk][nn] = pa0;  *(float4*)&As[kk + 8][nn] = pa1;
        *(float4*)&Bs[kk][nn] = pb0;  *(float4*)&Bs[kk + 8][nn] = pb1;
        __syncthreads();
        int kn = k0 + 16;
        if (kn < c) {   // prefetch next chunk overlapping compute
            pa0 = *(const float4*)&Xb[(size_t)(kn + kk) * NPAD + i0 + nn];
            pa1 = *(const float4*)&Xb[(size_t)(kn + kk + 8) * NPAD + i0 + nn];
            pb0 = *(const float4*)&Yb[(size_t)(kn + kk) * NPAD + j0 + nn];
            pb1 = *(const float4*)&Yb[(size_t)(kn + kk + 8) * NPAD + j0 + nn];
        }
#pragma unroll
        for (int k = 0; k < 16; k++) {
            float4 a0 = *(const float4*)&As[k][ty * 8];
            float4 a1 = *(const float4*)&As[k][ty * 8 + 4];
            float4 b0 = *(const float4*)&Bs[k][tx * 4];        // conflict-free: contiguous 256B
            float4 b1 = *(const float4*)&Bs[k][64 + tx * 4];
            float av[8] = {a0.x, a0.y, a0.z, a0.w, a1.x, a1.y, a1.z, a1.w};
            float bv[8] = {b0.x, b0.y, b0.z, b0.w, b1.x, b1.y, b1.z, b1.w};
#pragma unroll
            for (int i = 0; i < 8; i++)
#pragma unroll
                for (int j = 0; j < 8; j++) acc[i][j] += av[i] * bv[j];
        }
        __syncthreads();
    }

    // epilogue: cosine distance + tile-local min reduction
    __shared__ unsigned srow[128], scol[128];
    if (threadIdx.x < 128) { srow[threadIdx.x] = 0x7F7FFFFFu; scol[threadIdx.x] = 0x7F7FFFFFu; }
    __syncthreads();
    const float* nX = g_normX + (lvl * 8 + b) * 1024;
    const float* nY = g_normY + (lvl * 8 + b) * 1024;
    float nx[8], ny[8];
#pragma unroll
    for (int i = 0; i < 8; i++) nx[i] = nX[i0 + ty * 8 + i] + EPSF;
#pragma unroll
    for (int j = 0; j < 8; j++) ny[j] = nY[j0 + colofs(tx, j)] + EPSF;

    float colm[8];
#pragma unroll
    for (int j = 0; j < 8; j++) colm[j] = 3.402823466e+38f;
#pragma unroll
    for (int i = 0; i < 8; i++) {
        int gi = i0 + ty * 8 + i;
        bool iv = gi < N;
        float rowm = 3.402823466e+38f;
#pragma unroll
        for (int j = 0; j < 8; j++) {
            int gj = j0 + colofs(tx, j);
            float d = 1.0f - acc[i][j] / nx[i] / ny[j];   // matches ref's double division
            if (gj < N) {
                rowm = fminf(rowm, d);
                if (iv) colm[j] = fminf(colm[j], d);
            }
        }
        if (iv && rowm < 3.402823466e+38f) atomicMin(&srow[ty * 8 + i], __float_as_uint(rowm));
    }
#pragma unroll
    for (int j = 0; j < 8; j++)
        if (colm[j] < 3.402823466e+38f) atomicMin(&scol[colofs(tx, j)], __float_as_uint(colm[j]));
    __syncthreads();
    if (threadIdx.x < 128) {
        int gi = i0 + threadIdx.x, gj = j0 + threadIdx.x;
        if (gi < N) atomicMin(&g_rowmin[(lvl * 8 + b) * 1024 + gi], srow[threadIdx.x]);
        if (gj < N) atomicMin(&g_colmin[(lvl * 8 + b) * 1024 + gj], scol[threadIdx.x]);
    }
}

// ---------------- covariance pass: gram-shaped GEMM over transposed data ----------------
// pass 0: cov tile from XT -> g_cxs.  pass 1: cov tile from YT, accumulate w*|cx-cy|.
__global__ void __launch_bounds__(256, 2) covpass_kernel(int c, int N, int off, int lvl, int pass) {
    int a0 = blockIdx.y * 128, b0 = blockIdx.x * 128;
    if (a0 > b0) return;                         // upper-triangle tiles only
    int b = blockIdx.z;
    const float* __restrict__ T = (pass ? g_YT : g_XT) + off + (size_t)b * c * NPAD;
    const float* __restrict__ mu = (pass ? g_meanY : g_meanX) + (lvl * 8 + b) * 512;
    float* cxs = g_cxs + (size_t)b * 262144;     // pitch 512
    __shared__ float As[16][128], Bs[16][128];
    int tx = threadIdx.x & 15, ty = threadIdx.x >> 4;
    float acc[8][8];
#pragma unroll
    for (int i = 0; i < 8; i++)
#pragma unroll
        for (int j = 0; j < 8; j++) acc[i][j] = 0.f;

    int kk = threadIdx.x >> 5;
    int nn = (threadIdx.x & 31) * 4;

    // rows of T have length c; tile width 128 may overrun row for c=64 — reads stay
    // inside the scratch arrays and are masked out in the epilogue.
    float4 pa0 = *(const float4*)&T[(size_t)kk * c + a0 + nn];
    float4 pa1 = *(const float4*)&T[(size_t)(kk + 8) * c + a0 + nn];
    float4 pb0 = *(const float4*)&T[(size_t)kk * c + b0 + nn];
    float4 pb1 = *(const float4*)&T[(size_t)(kk + 8) * c + b0 + nn];

    for (int k0 = 0; k0 < NPAD; k0 += 16) {
        *(float4*)&As[kk][nn] = pa0;  *(float4*)&As[kk + 8][nn] = pa1;
        *(float4*)&Bs[kk][nn] = pb0;  *(float4*)&Bs[kk + 8][nn] = pb1;
        __syncthreads();
        int kn = k0 + 16;
        if (kn < NPAD) {
            pa0 = *(const float4*)&T[(size_t)(kn + kk) * c + a0 + nn];
            pa1 = *(const float4*)&T[(size_t)(kn + kk + 8) * c + a0 + nn];
            pb0 = *(const float4*)&T[(size_t)(kn + kk) * c + b0 + nn];
            pb1 = *(const float4*)&T[(size_t)(kn + kk + 8) * c + b0 + nn];
        }
#pragma unroll
        for (int k = 0; k < 16; k++) {
            float4 a0_ = *(const float4*)&As[k][ty * 8];
            float4 a1_ = *(const float4*)&As[k][ty * 8 + 4];
            float4 b0_ = *(const float4*)&Bs[k][tx * 4];
            float4 b1_ = *(const float4*)&Bs[k][64 + tx * 4];
            float av[8] = {a0_.x, a0_.y, a0_.z, a0_.w, a1_.x, a1_.y, a1_.z, a1_.w};
            float bv[8] = {b0_.x, b0_.y, b0_.z, b0_.w, b1_.x, b1_.y, b1_.z, b1_.w};
#pragma unroll
            for (int i = 0; i < 8; i++)
#pragma unroll
                for (int j = 0; j < 8; j++) acc[i][j] += av[i] * bv[j];
        }
        __syncthreads();
    }

    float inv = 1.0f / (float)(N - 1), fN = (float)N;
    float ma[8], mb[8];
#pragma unroll
    for (int i = 0; i < 8; i++) ma[i] = mu[a0 + ty * 8 + i];
#pragma unroll
    for (int j = 0; j < 8; j++) mb[j] = mu[b0 + colofs(tx, j)];

    if (pass == 0) {
#pragma unroll
        for (int i = 0; i < 8; i++) {
            int ga = a0 + ty * 8 + i;
#pragma unroll
            for (int j = 0; j < 8; j++) {
                int gb = b0 + colofs(tx, j);
                cxs[(size_t)ga * 512 + gb] = (acc[i][j] - fN * ma[i] * mb[j]) * inv;
            }
        }
    } else {
        float local = 0.f;
#pragma unroll
        for (int i = 0; i < 8; i++) {
            int ga = a0 + ty * 8 + i;
#pragma unroll
            for (int j = 0; j < 8; j++) {
                int gb = b0 + colofs(tx, j);
                if (ga < c && gb < c && ga <= gb) {
                    float cy = (acc[i][j] - fN * ma[i] * mb[j]) * inv;
                    float cx = cxs[(size_t)ga * 512 + gb];
                    local += (ga < gb ? 2.f : 1.f) * fabsf(cx - cy);
                }
            }
        }
#pragma unroll
        for (int o = 16; o; o >>= 1) local += __shfl_xor_sync(0xFFFFFFFFu, local, o);
        __shared__ float red[8];
        if ((threadIdx.x & 31) == 0) red[threadIdx.x >> 5] = local;
        __syncthreads();
        if (threadIdx.x == 0) {
            float s = 0.f;
            for (int i = 0; i < 8; i++) s += red[i];
            atomicAdd(&g_covabs[lvl * 8 + b], s);
        }
    }
}

// ---------------- style (max of mean-mins) + mean-abs-diff term, per (b, level) ----------------
__global__ void stylered_kernel() {
    int b = blockIdx.x, l = blockIdx.y;
    const int cs_[4] = {64, 128, 256, 512};
    const int Ns_[4] = {1000, 1000, 1000, 1024};
    int c = cs_[l], N = Ns_[l];
    int base = (l * 8 + b) * 1024;
    float rs = 0.f, csu = 0.f;
    for (int i = threadIdx.x; i < N; i += 256) {
        rs  += __uint_as_float(g_rowmin[base + i]);
        csu += __uint_as_float(g_colmin[base + i]);
    }
    int mbase = (l * 8 + b) * 512;
    float ms = 0.f;
    for (int ch = threadIdx.x; ch < c; ch += 256)
        ms += fabsf(g_meanX[mbase + ch] - g_meanY[mbase + ch]);

    __shared__ float s1[256], s2[256], s3[256];
    int t = threadIdx.x;
    s1[t] = rs; s2[t] = csu; s3[t] = ms;
    __syncthreads();
    for (int o = 128; o; o >>= 1) {
        if (t < o) { s1[t] += s1[t + o]; s2[t] += s2[t + o]; s3[t] += s3[t + o]; }
        __syncthreads();
    }
    if (t == 0) {
        float style = fmaxf(s1[0] / (float)N, s2[0] / (float)N);
        g_sm[l * 8 + b] = style + s3[0] / (float)c;
    }
}

// ---------------- final scalar ----------------
__global__ void final_kernel(float* __restrict__ out) {
    int t = threadIdx.x;   // 32 threads = 4 levels * 8 batches
    const int cs_[4] = {64, 128, 256, 512};
    int l = t >> 3;
    float cc = (float)cs_[l];
    float v = g_sm[t] + g_covabs[t] / (cc * cc);
#pragma unroll
    for (int o = 16; o; o >>= 1) v += __shfl_xor_sync(0xFFFFFFFFu, v, o);
    if (t == 0) out[0] = v * 0.125f;   // mean over batch
}

// ---------------- host launcher ----------------
extern "C" void kernel_launch(void* const* d_in, const int* in_sizes, int n_in,
                              void* d_out, int out_size) {
    (void)out_size;
    const float* tgt[4] = {nullptr, nullptr, nullptr, nullptr};
    const float* gen[4] = {nullptr, nullptr, nullptr, nullptr};
    const int* idxp[3]  = {nullptr, nullptr, nullptr};
    int ni = 0;
    for (int i = 0; i < n_in; i++) {
        int lvl = -1;
        switch (in_sizes[i]) {
            case 33554432: lvl = 0; break;   // 8*64*256*256
            case 16777216: lvl = 1; break;   // 8*128*128*128
            case 8388608:  lvl = 2; break;   // 8*256*64*64
            case 4194304:  lvl = 3; break;   // 8*512*32*32
            case 8000: if (ni < 3) idxp[ni++] = (const int*)d_in[i]; break;
            default: break;
        }
        if (lvl >= 0) {
            if (!tgt[lvl]) tgt[lvl] = (const float*)d_in[i];
            else           gen[lvl] = (const float*)d_in[i];
        }
    }

    const int cs[4]   = {64, 128, 256, 512};
    const int Ns[4]   = {1000, 1000, 1000, 1024};
    const int hws[4]  = {65536, 16384, 4096, 1024};
    const int offs[4] = {0, 524288, 1572864, 3670016};

    init_kernel<<<256, 256>>>();
    for (int l = 0; l < 4; l++)
        gather_kernel<<<dim3(cs[l] * 4, 8, 2), 256>>>(
            tgt[l], gen[l], (l < 3) ? idxp[l] : nullptr, cs[l], hws[l], Ns[l], offs[l]);
    for (int l = 0; l < 4; l++)
        transpose_kernel<<<dim3(cs[l] / 32, 32, 16), dim3(32, 8)>>>(cs[l], offs[l]);
    for (int l = 0; l < 4; l++) {
        norms_kernel<<<dim3(4, 8, 2), 256>>>(cs[l], offs[l], l);
        means_kernel<<<dim3(cs[l] / 8, 8, 2), 256>>>(cs[l], Ns[l], offs[l], l);
    }
    for (int l = 0; l < 4; l++)
        gram_kernel<<<dim3(8, 8, 8), 256>>>(cs[l], Ns[l], offs[l], l);
    for (int l = 0; l < 4; l++) {
        int gt = (cs[l] + 127) / 128;
        covpass_kernel<<<dim3(gt, gt, 8), 256>>>(cs[l], Ns[l], offs[l], l, 0);
        covpass_kernel<<<dim3(gt, gt, 8), 256>>>(cs[l], Ns[l], offs[l], l, 1);
    }
    stylered_kernel<<<dim3(8, 4), 256>>>();
    final_kernel<<<1, 32>>>((float*)d_out);
}

// round 12
// speedup vs baseline: 1.8794x; 1.7705x over previous
#include <cuda_runtime.h>
#include <math.h>

#define EPSF 1e-10f
#define NPAD 1024

// ---------------- scratch (device globals; no allocation allowed) ----------------
// gathered points, channel-major: [level][b][ch][n], n padded to 1024 with zeros
__device__ float g_X[7864320];   // sum_l 8*c_l*1024
__device__ float g_Y[7864320];
__device__ float g_normX[4 * 8 * 1024];
__device__ float g_normY[4 * 8 * 1024];
__device__ float g_meanX[4 * 8 * 512];
__device__ float g_meanY[4 * 8 * 512];
__device__ unsigned g_rowmin[4 * 8 * 1024];
__device__ unsigned g_colmin[4 * 8 * 1024];
// split-K partial Gram slices: per level, (S= 1024/c) slices of [8][c][c]; since
// 8*S*c*c == 8*c*1024, per-level offsets coincide with offs[] of g_X. 30MB each.
__device__ float g_covPX[7864320];
__device__ float g_covPY[7864320];
__device__ float g_covabs[32];   // [l*8+b]  sum |covX-covY|
__device__ float g_sm[32];       // [l*8+b]  style + mean-diff term

// ---------------- init ----------------
__global__ void init_kernel() {
    int t = blockIdx.x * 256 + threadIdx.x;
    if (t < 4 * 8 * 1024) {
        g_rowmin[t] = 0x7F7FFFFFu;   // FLT_MAX bits; distances > 0 so uint order == float order
        g_colmin[t] = 0x7F7FFFFFu;
    }
    if (t < 32) g_covabs[t] = 0.f;
}

// ---------------- gather: feat (B,c,h,w) + idx -> X[ch][1024] zero-padded ----------------
__global__ void gather_kernel(const float* __restrict__ tgt, const float* __restrict__ gen,
                              const int* __restrict__ idx, int c, int hw, int N, int off) {
    int b = blockIdx.y, tsel = blockIdx.z;
    const float* src = tsel ? gen : tgt;
    float* dst = (tsel ? g_Y : g_X) + off;
    int t = blockIdx.x * 256 + threadIdx.x;     // grid.x = c*4 so t < c*1024 always
    int ch = t >> 10, n = t & 1023;
    float v = 0.f;
    if (n < N) {
        int pos = idx ? idx[b * N + n] : n;
        v = src[((size_t)b * c + ch) * hw + pos];
    }
    dst[((size_t)b * c + ch) * NPAD + n] = v;   // coalesced over n
}

// ---------------- per-point L2 norms ----------------
__global__ void norms_kernel(int c, int off, int lvl) {
    int b = blockIdx.y, tsel = blockIdx.z;
    const float* src = (tsel ? g_Y : g_X) + off + (size_t)b * c * NPAD;
    float* dst = (tsel ? g_normY : g_normX) + (lvl * 8 + b) * 1024;
    int n = blockIdx.x * 256 + threadIdx.x;
    float s = 0.f;
    for (int ch = 0; ch < c; ch++) { float v = src[ch * NPAD + n]; s += v * v; }
    dst[n] = sqrtf(s);
}

// ---------------- per-channel means (warp per channel) ----------------
__global__ void means_kernel(int c, int N, int off, int lvl) {
    int b = blockIdx.y, tsel = blockIdx.z;
    const float* src = (tsel ? g_Y : g_X) + off + (size_t)b * c * NPAD;
    float* dst = (tsel ? g_meanY : g_meanX) + (lvl * 8 + b) * 512;
    int ch = blockIdx.x * 8 + (threadIdx.x >> 5);
    int lane = threadIdx.x & 31;
    if (ch >= c) return;
    float s = 0.f;
    for (int n = lane; n < NPAD; n += 32) s += src[ch * NPAD + n];
#pragma unroll
    for (int o = 16; o; o >>= 1) s += __shfl_xor_sync(0xFFFFFFFFu, s, o);
    if (lane == 0) dst[ch] = s / (float)N;
}

// ---------------- Gram + cosine distance + row/col min (64x64 tile, 4x4/thread) ----------------
// (verbatim round-6 kernel — measured good)
__global__ void __launch_bounds__(256) gram_kernel(int c, int N, int off, int lvl) {
    int b = blockIdx.z;
    const float* Xb = g_X + off + (size_t)b * c * NPAD;
    const float* Yb = g_Y + off + (size_t)b * c * NPAD;
    int i0 = blockIdx.y * 64, j0 = blockIdx.x * 64;
    __shared__ float As[16][64], Bs[16][64];
    int tx = threadIdx.x & 15, ty = threadIdx.x >> 4;
    float acc[4][4];
#pragma unroll
    for (int i = 0; i < 4; i++)
#pragma unroll
        for (int j = 0; j < 4; j++) acc[i][j] = 0.f;

    for (int k0 = 0; k0 < c; k0 += 16) {
#pragma unroll
        for (int r = 0; r < 4; r++) {
            int id = r * 256 + threadIdx.x;
            int kk = id >> 6, nn = id & 63;
            As[kk][nn] = Xb[(k0 + kk) * NPAD + i0 + nn];
            Bs[kk][nn] = Yb[(k0 + kk) * NPAD + j0 + nn];
        }
        __syncthreads();
#pragma unroll
        for (int k = 0; k < 16; k++) {
            float4 a4 = *reinterpret_cast<const float4*>(&As[k][ty * 4]);
            float4 b4 = *reinterpret_cast<const float4*>(&Bs[k][tx * 4]);
            float a[4] = {a4.x, a4.y, a4.z, a4.w};
            float bb[4] = {b4.x, b4.y, b4.z, b4.w};
#pragma unroll
            for (int i = 0; i < 4; i++)
#pragma unroll
                for (int j = 0; j < 4; j++) acc[i][j] += a[i] * bb[j];
        }
        __syncthreads();
    }

    __shared__ unsigned srow[64], scol[64];
    if (threadIdx.x < 64) { srow[threadIdx.x] = 0x7F7FFFFFu; scol[threadIdx.x] = 0x7F7FFFFFu; }
    __syncthreads();
    const float* nX = g_normX + (lvl * 8 + b) * 1024;
    const float* nY = g_normY + (lvl * 8 + b) * 1024;
    float nx[4], ny[4];
#pragma unroll
    for (int i = 0; i < 4; i++) {
        nx[i] = nX[i0 + ty * 4 + i] + EPSF;
        ny[i] = nY[j0 + tx * 4 + i] + EPSF;
    }
#pragma unroll
    for (int i = 0; i < 4; i++) {
        int gi = i0 + ty * 4 + i;
#pragma unroll
        for (int j = 0; j < 4; j++) {
            int gj = j0 + tx * 4 + j;
            if (gi < N && gj < N) {
                float d = 1.0f - acc[i][j] / nx[i] / ny[j];   // matches ref's double division
                unsigned u = __float_as_uint(d);              // d > 0 for random gaussian features
                atomicMin(&srow[ty * 4 + i], u);
                atomicMin(&scol[tx * 4 + j], u);
            }
        }
    }
    __syncthreads();
    if (threadIdx.x < 64) {
        int gi = i0 + threadIdx.x, gj = j0 + threadIdx.x;
        if (gi < N) atomicMin(&g_rowmin[(lvl * 8 + b) * 1024 + gi], srow[threadIdx.x]);
        if (gj < N) atomicMin(&g_colmin[(lvl * 8 + b) * 1024 + gj], scol[threadIdx.x]);
    }
}

// ---------------- split-K fused partial Grams: X^T X and Y^T Y over one K chunk ----------------
// Round-6 cov mainloop, but each block owns K range [s*c, (s+1)*c) and writes raw
// partial sums to its own slice (no atomics, no zero-init, deterministic).
// grid: (c/64, c/64, 8 * (1024/c)); z = s*8 + b.
__global__ void __launch_bounds__(256) covgram_kernel(int c, int off, int lvl) {
    int a0 = blockIdx.y * 64, b0 = blockIdx.x * 64;
    if (a0 > b0) return;                        // upper-triangle tiles only
    int b = blockIdx.z & 7, s = blockIdx.z >> 3;
    int kbeg = s * c;                           // Kc = c  (S = 1024/c)
    const float* Xb = g_X + off + (size_t)b * c * NPAD;
    const float* Yb = g_Y + off + (size_t)b * c * NPAD;
    __shared__ float Ax[64][17], Bx[64][17], Ay[64][17], By[64][17];
    int tx = threadIdx.x & 15, ty = threadIdx.x >> 4;
    float accx[4][4], accy[4][4];
#pragma unroll
    for (int i = 0; i < 4; i++)
#pragma unroll
        for (int j = 0; j < 4; j++) { accx[i][j] = 0.f; accy[i][j] = 0.f; }

    int la = threadIdx.x >> 2;                  // 0..63  (row within tile)
    int lk = (threadIdx.x & 3) * 4;             // float4 slot within 16-wide K chunk

    for (int k0 = kbeg; k0 < kbeg + c; k0 += 16) {
        float4 v;
        v = *reinterpret_cast<const float4*>(&Xb[(a0 + la) * NPAD + k0 + lk]);
        Ax[la][lk + 0] = v.x; Ax[la][lk + 1] = v.y; Ax[la][lk + 2] = v.z; Ax[la][lk + 3] = v.w;
        v = *reinterpret_cast<const float4*>(&Xb[(b0 + la) * NPAD + k0 + lk]);
        Bx[la][lk + 0] = v.x; Bx[la][lk + 1] = v.y; Bx[la][lk + 2] = v.z; Bx[la][lk + 3] = v.w;
        v = *reinterpret_cast<const float4*>(&Yb[(a0 + la) * NPAD + k0 + lk]);
        Ay[la][lk + 0] = v.x; Ay[la][lk + 1] = v.y; Ay[la][lk + 2] = v.z; Ay[la][lk + 3] = v.w;
        v = *reinterpret_cast<const float4*>(&Yb[(b0 + la) * NPAD + k0 + lk]);
        By[la][lk + 0] = v.x; By[la][lk + 1] = v.y; By[la][lk + 2] = v.z; By[la][lk + 3] = v.w;
        __syncthreads();
#pragma unroll
        for (int k = 0; k < 16; k++) {
            float xa[4], xb[4], ya[4], yb[4];
#pragma unroll
            for (int i = 0; i < 4; i++) {
                xa[i] = Ax[ty * 4 + i][k];
                ya[i] = Ay[ty * 4 + i][k];
                xb[i] = Bx[tx * 4 + i][k];
                yb[i] = By[tx * 4 + i][k];
            }
#pragma unroll
            for (int i = 0; i < 4; i++)
#pragma unroll
                for (int j = 0; j < 4; j++) {
                    accx[i][j] += xa[i] * xb[j];
                    accy[i][j] += ya[i] * yb[j];
                }
        }
        __syncthreads();
    }

    // store raw partial sums into this (s,b) slice
    float* px = g_covPX + off + (size_t)(s * 8 + b) * c * c;
    float* py = g_covPY + off + (size_t)(s * 8 + b) * c * c;
#pragma unroll
    for (int i = 0; i < 4; i++) {
        int ga = a0 + ty * 4 + i;
#pragma unroll
        for (int j = 0; j < 4; j++) {
            int gb = b0 + tx * 4 + j;
            px[(size_t)ga * c + gb] = accx[i][j];
            py[(size_t)ga * c + gb] = accy[i][j];
        }
    }
}

// ---------------- sum slices, mean-correct, accumulate w*|covX - covY| ----------------
__global__ void covabs_kernel(int c, int off, int lvl, int N) {
    int b = blockIdx.y;
    int t = blockIdx.x * 256 + threadIdx.x;     // grid.x = c*c/256
    float local = 0.f;
    int ga = t / c, gb = t % c;
    if (ga <= gb) {
        int S = NPAD / c;
        float sx = 0.f, sy = 0.f;
        for (int s = 0; s < S; s++) {
            size_t idx = (size_t)off + (size_t)(s * 8 + b) * c * c + t;
            sx += g_covPX[idx];
            sy += g_covPY[idx];
        }
        const float* mX = g_meanX + (lvl * 8 + b) * 512;
        const float* mY = g_meanY + (lvl * 8 + b) * 512;
        float inv = 1.0f / (float)(N - 1), fN = (float)N;
        float cx = (sx - fN * mX[ga] * mX[gb]) * inv;
        float cy = (sy - fN * mY[ga] * mY[gb]) * inv;
        local = (ga < gb ? 2.f : 1.f) * fabsf(cx - cy);
    }
#pragma unroll
    for (int o = 16; o; o >>= 1) local += __shfl_xor_sync(0xFFFFFFFFu, local, o);
    __shared__ float red[8];
    if ((threadIdx.x & 31) == 0) red[threadIdx.x >> 5] = local;
    __syncthreads();
    if (threadIdx.x == 0) {
        float ssum = 0.f;
        for (int i = 0; i < 8; i++) ssum += red[i];
        atomicAdd(&g_covabs[lvl * 8 + b], ssum);
    }
}

// ---------------- style (max of mean-mins) + mean-abs-diff term, per (b, level) ----------------
__global__ void stylered_kernel() {
    int b = blockIdx.x, l = blockIdx.y;
    const int cs_[4] = {64, 128, 256, 512};
    const int Ns_[4] = {1000, 1000, 1000, 1024};
    int c = cs_[l], N = Ns_[l];
    int base = (l * 8 + b) * 1024;
    float rs = 0.f, csu = 0.f;
    for (int i = threadIdx.x; i < N; i += 256) {
        rs  += __uint_as_float(g_rowmin[base + i]);
        csu += __uint_as_float(g_colmin[base + i]);
    }
    int mbase = (l * 8 + b) * 512;
    float ms = 0.f;
    for (int ch = threadIdx.x; ch < c; ch += 256)
        ms += fabsf(g_meanX[mbase + ch] - g_meanY[mbase + ch]);

    __shared__ float s1[256], s2[256], s3[256];
    int t = threadIdx.x;
    s1[t] = rs; s2[t] = csu; s3[t] = ms;
    __syncthreads();
    for (int o = 128; o; o >>= 1) {
        if (t < o) { s1[t] += s1[t + o]; s2[t] += s2[t + o]; s3[t] += s3[t + o]; }
        __syncthreads();
    }
    if (t == 0) {
        float style = fmaxf(s1[0] / (float)N, s2[0] / (float)N);
        g_sm[l * 8 + b] = style + s3[0] / (float)c;
    }
}

// ---------------- final scalar ----------------
__global__ void final_kernel(float* __restrict__ out) {
    int t = threadIdx.x;   // 32 threads = 4 levels * 8 batches
    const int cs_[4] = {64, 128, 256, 512};
    int l = t >> 3;
    float cc = (float)cs_[l];
    float v = g_sm[t] + g_covabs[t] / (cc * cc);
#pragma unroll
    for (int o = 16; o; o >>= 1) v += __shfl_xor_sync(0xFFFFFFFFu, v, o);
    if (t == 0) out[0] = v * 0.125f;   // mean over batch
}

// ---------------- host launcher ----------------
extern "C" void kernel_launch(void* const* d_in, const int* in_sizes, int n_in,
                              void* d_out, int out_size) {
    (void)out_size;
    const float* tgt[4] = {nullptr, nullptr, nullptr, nullptr};
    const float* gen[4] = {nullptr, nullptr, nullptr, nullptr};
    const int* idxp[3]  = {nullptr, nullptr, nullptr};
    int ni = 0;
    for (int i = 0; i < n_in; i++) {
        int lvl = -1;
        switch (in_sizes[i]) {
            case 33554432: lvl = 0; break;   // 8*64*256*256
            case 16777216: lvl = 1; break;   // 8*128*128*128
            case 8388608:  lvl = 2; break;   // 8*256*64*64
            case 4194304:  lvl = 3; break;   // 8*512*32*32
            case 8000: if (ni < 3) idxp[ni++] = (const int*)d_in[i]; break;
            default: break;
        }
        if (lvl >= 0) {
            if (!tgt[lvl]) tgt[lvl] = (const float*)d_in[i];
            else           gen[lvl] = (const float*)d_in[i];
        }
    }

    const int cs[4]   = {64, 128, 256, 512};
    const int Ns[4]   = {1000, 1000, 1000, 1024};
    const int hws[4]  = {65536, 16384, 4096, 1024};
    const int offs[4] = {0, 524288, 1572864, 3670016};

    init_kernel<<<256, 256>>>();
    for (int l = 0; l < 4; l++)
        gather_kernel<<<dim3(cs[l] * 4, 8, 2), 256>>>(
            tgt[l], gen[l], (l < 3) ? idxp[l] : nullptr, cs[l], hws[l], Ns[l], offs[l]);
    for (int l = 0; l < 4; l++) {
        norms_kernel<<<dim3(4, 8, 2), 256>>>(cs[l], offs[l], l);
        means_kernel<<<dim3(cs[l] / 8, 8, 2), 256>>>(cs[l], Ns[l], offs[l], l);
    }
    // split-K partial Grams first (independent of means), then gram, then covabs
    for (int l = 0; l < 4; l++)
        covgram_kernel<<<dim3(cs[l] / 64, cs[l] / 64, 8 * (NPAD / cs[l])), 256>>>(
            cs[l], offs[l], l);
    for (int l = 0; l < 4; l++)
        gram_kernel<<<dim3(16, 16, 8), 256>>>(cs[l], Ns[l], offs[l], l);
    for (int l = 0; l < 4; l++)
        covabs_kernel<<<dim3(cs[l] * cs[l] / 256, 8), 256>>>(cs[l], offs[l], l, Ns[l]);
    stylered_kernel<<<dim3(8, 4), 256>>>();
    final_kernel<<<1, 32>>>((float*)d_out);
}

// round 15
// speedup vs baseline: 1.9258x; 1.0247x over previous
#include <cuda_runtime.h>
#include <cuda_bf16.h>
#include <math.h>
#include <stdint.h>

#define EPSF 1e-10f
#define NPAD 1024
#define FLTMAXF 3.402823466e+38f

// ---------------- scratch (device globals; no allocation allowed) ----------------
__device__ float g_X[7864320];   // [level][b][ch][n], n zero-padded to 1024
__device__ float g_Y[7864320];
__device__ __nv_bfloat16 g_XThi[7864320];  // transposed [level][b][n][ch], bf16 hi
__device__ __nv_bfloat16 g_XTlo[7864320];  // bf16 lo residual
__device__ __nv_bfloat16 g_YThi[7864320];
__device__ __nv_bfloat16 g_YTlo[7864320];
__device__ float g_normX[4 * 8 * 1024];
__device__ float g_normY[4 * 8 * 1024];
__device__ float g_meanX[4 * 8 * 512];
__device__ float g_meanY[4 * 8 * 512];
__device__ unsigned g_rowmin[4 * 8 * 1024];
__device__ unsigned g_colmin[4 * 8 * 1024];
__device__ float g_covPX[7864320];   // split-K partial Gram slices
__device__ float g_covPY[7864320];
__device__ float g_covabs[32];
__device__ float g_sm[32];

// ---------------- ptx helpers ----------------
__device__ __forceinline__ uint32_t smem_u32(const void* p) {
    uint32_t a;
    asm("{ .reg .u64 t; cvta.to.shared.u64 t, %1; cvt.u32.u64 %0, t; }" : "=r"(a) : "l"(p));
    return a;
}
__device__ __forceinline__ uint32_t elect1() {
    uint32_t p;
    asm volatile("{ .reg .pred p; elect.sync _|p, 0xFFFFFFFF; selp.b32 %0, 1, 0, p; }" : "=r"(p));
    return p;
}
#define SWZ128(x) ((x) ^ (((x) >> 3) & 0x70))
// SW128 K-major desc: layout=2, version=1, SBO=64, LBO=1 (validated in examples)
#define DESC_BASE ((uint64_t(2) << 61) | (uint64_t(1) << 46) | (uint64_t(64) << 32) | (uint64_t(1) << 16))
#define MK_DESC(a) (DESC_BASE | ((uint64_t)((a) >> 4) & 0x3FFF))

#define MBAR_INIT(mb, n) asm volatile("mbarrier.init.shared.b64 [%0], %1;" :: "r"(mb), "r"(n) : "memory")
#define MBAR_WAIT(mb, ph) do { \
    uint32_t _m = (mb), _p = (ph), _d; \
    asm volatile("{ .reg .pred p; mbarrier.try_wait.parity.acquire.cta.shared::cta.b64 p, [%1], %2; selp.b32 %0, 1, 0, p; }" \
                 : "=r"(_d) : "r"(_m), "r"(_p) : "memory"); \
    if (!_d) { \
        asm volatile("{ .reg .pred P1;\nWL_%=:\n mbarrier.try_wait.parity.acquire.cta.shared::cta.b64 P1, [%0], %1, 0x989680;\n @P1 bra.uni WD_%=;\n bra.uni WL_%=;\nWD_%=:\n}" \
                     :: "r"(_m), "r"(_p) : "memory"); \
    } } while (0)
#define FENCE_ASYNC()    asm volatile("fence.proxy.async.shared::cta;" ::: "memory")

// ---- tcgen05 (sm_103a-only; everything that touches these lives behind the arch guard) ----
#if defined(__CUDA_ARCH__) && defined(__CUDA_ARCH_FEAT_SM103_ALL)
#define HAS_TCGEN05 1
#endif

#define T5_ALLOC(sa, n)  asm volatile("tcgen05.alloc.cta_group::1.sync.aligned.shared::cta.b32 [%0], %1;" :: "r"(sa), "r"(n) : "memory")
#define T5_RELINQ()      asm volatile("tcgen05.relinquish_alloc_permit.cta_group::1.sync.aligned;")
#define T5_DEALLOC(t, n) asm volatile("tcgen05.dealloc.cta_group::1.sync.aligned.b32 %0, %1;" :: "r"(t), "r"(n))
#define T5_COMMIT(mb)    asm volatile("tcgen05.commit.cta_group::1.mbarrier::arrive::one.shared::cluster.b64 [%0];" :: "r"(mb) : "memory")
#define T5_FENCE_AFTER() asm volatile("tcgen05.fence::after_thread_sync;" ::: "memory")
#define T5_WAIT_LD()     asm volatile("tcgen05.wait::ld.sync.aligned;" ::: "memory")
#define T5_LD_X32(r, ta) \
    asm volatile("tcgen05.ld.sync.aligned.32x32b.x32.b32 " \
        "{%0,%1,%2,%3,%4,%5,%6,%7,%8,%9,%10,%11,%12,%13,%14,%15," \
        "%16,%17,%18,%19,%20,%21,%22,%23,%24,%25,%26,%27,%28,%29,%30,%31}, [%32];" \
        : "=r"((r)[0]),"=r"((r)[1]),"=r"((r)[2]),"=r"((r)[3]),"=r"((r)[4]),"=r"((r)[5]),"=r"((r)[6]),"=r"((r)[7]), \
          "=r"((r)[8]),"=r"((r)[9]),"=r"((r)[10]),"=r"((r)[11]),"=r"((r)[12]),"=r"((r)[13]),"=r"((r)[14]),"=r"((r)[15]), \
          "=r"((r)[16]),"=r"((r)[17]),"=r"((r)[18]),"=r"((r)[19]),"=r"((r)[20]),"=r"((r)[21]),"=r"((r)[22]),"=r"((r)[23]), \
          "=r"((r)[24]),"=r"((r)[25]),"=r"((r)[26]),"=r"((r)[27]),"=r"((r)[28]),"=r"((r)[29]),"=r"((r)[30]),"=r"((r)[31]) \
        : "r"(ta))

#ifdef HAS_TCGEN05
__device__ __forceinline__ void mma_f16_ss_cg1(uint32_t d, uint64_t a, uint64_t b,
                                               uint32_t idesc, uint32_t en) {
    asm volatile(
        "{\n\t.reg .pred p;\n\tsetp.ne.u32 p, %5, 0;\n\t"
        "tcgen05.mma.cta_group::1.kind::f16 [%0], %1, %2, %3, {%4, %4, %4, %4}, p;\n\t}"
        :: "r"(d), "l"(a), "l"(b), "r"(idesc), "r"(0u), "r"(en) : "memory");
}
#endif

// idesc kind::f16: dtype=F32(1<<4), a=BF16(1<<7), b=BF16(1<<10), N/8<<17, M/16<<24
// M=128, N=128 (formula validated against test_mma.cu's 0x8080490 for M=128,N=32)
#define GRAM_IDESC ((1u << 4) | (1u << 7) | (1u << 10) | ((128u / 8) << 17) | ((128u / 16) << 24))

// ---------------- init ----------------
__global__ void init_kernel() {
    int t = blockIdx.x * 256 + threadIdx.x;
    if (t < 4 * 8 * 1024) {
        g_rowmin[t] = 0x7F7FFFFFu;   // FLT_MAX bits; distances > 0 so uint order == float order
        g_colmin[t] = 0x7F7FFFFFu;
    }
    if (t < 32) g_covabs[t] = 0.f;
}

// ---------------- gather ----------------
__global__ void gather_kernel(const float* __restrict__ tgt, const float* __restrict__ gen,
                              const int* __restrict__ idx, int c, int hw, int N, int off) {
    int b = blockIdx.y, tsel = blockIdx.z;
    const float* src = tsel ? gen : tgt;
    float* dst = (tsel ? g_Y : g_X) + off;
    int t = blockIdx.x * 256 + threadIdx.x;
    int ch = t >> 10, n = t & 1023;
    float v = 0.f;
    if (n < N) {
        int pos = idx ? idx[b * N + n] : n;
        v = src[((size_t)b * c + ch) * hw + pos];
    }
    dst[((size_t)b * c + ch) * NPAD + n] = v;
}

// ---------------- transpose + bf16 hi/lo split: [ch][n] fp32 -> [n][ch] bf16 x2 ----------------
__global__ void bfsplit_kernel(int c, int off) {
    __shared__ float tile[32][33];
    int b = blockIdx.z & 7, tsel = blockIdx.z >> 3;
    const float* src = (tsel ? g_Y : g_X) + off + (size_t)b * c * NPAD;
    __nv_bfloat16* dhi = (tsel ? g_YThi : g_XThi) + off + (size_t)b * c * NPAD;
    __nv_bfloat16* dlo = (tsel ? g_YTlo : g_XTlo) + off + (size_t)b * c * NPAD;
    int ch0 = blockIdx.x * 32, n0 = blockIdx.y * 32;
#pragma unroll
    for (int r = threadIdx.y; r < 32; r += 8)
        tile[r][threadIdx.x] = src[(size_t)(ch0 + r) * NPAD + n0 + threadIdx.x];
    __syncthreads();
#pragma unroll
    for (int r = threadIdx.y; r < 32; r += 8) {
        float v = tile[threadIdx.x][r];
        __nv_bfloat16 h = __float2bfloat16(v);
        __nv_bfloat16 l = __float2bfloat16(v - __bfloat162float(h));
        size_t o = (size_t)(n0 + r) * c + ch0 + threadIdx.x;
        dhi[o] = h;
        dlo[o] = l;
    }
}

// ---------------- per-point L2 norms ----------------
__global__ void norms_kernel(int c, int off, int lvl) {
    int b = blockIdx.y, tsel = blockIdx.z;
    const float* src = (tsel ? g_Y : g_X) + off + (size_t)b * c * NPAD;
    float* dst = (tsel ? g_normY : g_normX) + (lvl * 8 + b) * 1024;
    int n = blockIdx.x * 256 + threadIdx.x;
    float s = 0.f;
    for (int ch = 0; ch < c; ch++) { float v = src[ch * NPAD + n]; s += v * v; }
    dst[n] = sqrtf(s);
}

// ---------------- per-channel means ----------------
__global__ void means_kernel(int c, int N, int off, int lvl) {
    int b = blockIdx.y, tsel = blockIdx.z;
    const float* src = (tsel ? g_Y : g_X) + off + (size_t)b * c * NPAD;
    float* dst = (tsel ? g_meanY : g_meanX) + (lvl * 8 + b) * 512;
    int ch = blockIdx.x * 8 + (threadIdx.x >> 5);
    int lane = threadIdx.x & 31;
    if (ch >= c) return;
    float s = 0.f;
    for (int n = lane; n < NPAD; n += 32) s += src[ch * NPAD + n];
#pragma unroll
    for (int o = 16; o; o >>= 1) s += __shfl_xor_sync(0xFFFFFFFFu, s, o);
    if (lane == 0) dst[ch] = s / (float)N;
}

// ---------------- Gram + cosine distance + row/col min ----------------
// One kernel symbol, one launch config (grid 8x8x8, 256 thr, 67584B dyn smem):
//   sm_103a pass : tcgen05 bf16 hi/lo-split MMA, 128x128 tile
//   sm_103 pass  : scalar round-6 64x64/4x4 mainloop over the 4 subtiles
__global__ void __launch_bounds__(256) gram_mma_kernel(int c, int N, int off, int lvl) {
    extern __shared__ char smem[];
    int t = threadIdx.x;
    int b = blockIdx.z;
    int nb = (lvl * 8 + b) * 1024;

#ifdef HAS_TCGEN05
    // ================= tcgen05 path =================
    uint32_t sb = smem_u32(smem);
    int wid = t >> 5, lane = t & 31;
    int i0 = blockIdx.y * 128, j0 = blockIdx.x * 128;

    if (wid == 0) { T5_ALLOC(sb, 128); T5_RELINQ(); }
    __syncthreads();
    uint32_t tmem;
    asm volatile("ld.shared.b32 %0, [%1];" : "=r"(tmem) : "r"(sb));

    float* sny = (float*)(smem + 16);
    unsigned* scolb = (unsigned*)(smem + 528);
    if (t == 0) MBAR_INIT(sb + 8, 1);
    if (t < 128) {
        sny[t] = g_normY[nb + j0 + t] + EPSF;
        scolb[t] = 0x7F7FFFFFu;
    }
    __syncthreads();

    const __nv_bfloat16* ga[4] = {
        g_XThi + off + ((size_t)b * NPAD + i0) * c,
        g_XTlo + off + ((size_t)b * NPAD + i0) * c,
        g_YThi + off + ((size_t)b * NPAD + j0) * c,
        g_YTlo + off + ((size_t)b * NPAD + j0) * c
    };

    int nchunks = c / 64;
    for (int ch = 0; ch < nchunks; ch++) {
        int kc = ch * 64;
#pragma unroll
        for (int q = 0; q < 4; q++) {
            char* tb = smem + 2048 + q * 16384;
            const __nv_bfloat16* gp = ga[q] + kc;
#pragma unroll
            for (int r = 0; r < 4; r++) {
                int id = r * 256 + t;            // 0..1023
                int row = id >> 3, c16 = id & 7; // row 0..127, 16B chunk 0..7
                uint4 v = *(const uint4*)(gp + (size_t)row * c + c16 * 8);
                uint32_t bo = row * 128 + c16 * 16;
                *(uint4*)(tb + SWZ128(bo)) = v;
            }
        }
        __syncthreads();
        if (wid == 0 && elect1()) {
            FENCE_ASYNC();
            uint64_t dAh = MK_DESC(sb + 2048);
            uint64_t dAl = MK_DESC(sb + 2048 + 16384);
            uint64_t dBh = MK_DESC(sb + 2048 + 32768);
            uint64_t dBl = MK_DESC(sb + 2048 + 49152);
            uint64_t pa[3] = {dAh, dAh, dAl};
            uint64_t pb[3] = {dBh, dBl, dBh};
#pragma unroll
            for (int pi = 0; pi < 3; pi++)
#pragma unroll
                for (int ks = 0; ks < 4; ks++) {
                    uint32_t en = (ch > 0 || pi > 0 || ks > 0) ? 1u : 0u;
                    mma_f16_ss_cg1(tmem, pa[pi] + ks * 2, pb[pi] + ks * 2, GRAM_IDESC, en);
                }
            T5_COMMIT(sb + 8);
        }
        MBAR_WAIT(sb + 8, (uint32_t)(ch & 1));
        __syncthreads();   // all threads past wait before next chunk overwrites smem
    }
    T5_FENCE_AFTER();

    // epilogue: warps 0-3 read D rows (lane l of warp w -> row w*32+l), 2 halves of 64 cols
    if (t < 128) {
        int gi = i0 + wid * 32 + lane;
        bool iv = gi < N;
        float nx = g_normX[nb + gi] + EPSF;
        float rowm = FLTMAXF;
#pragma unroll
        for (int h = 0; h < 2; h++) {
            uint32_t r0[32], r1[32];
            T5_LD_X32(r0, tmem + h * 64);
            T5_LD_X32(r1, tmem + h * 64 + 32);
            T5_WAIT_LD();
#pragma unroll
            for (int j = 0; j < 64; j++) {
                int jj = h * 64 + j;
                int gj = j0 + jj;
                float g = __uint_as_float(j < 32 ? r0[j] : r1[j - 32]);
                float d = 1.0f - g / nx / sny[jj];     // matches ref's double division
                bool jv = gj < N;
                if (jv) rowm = fminf(rowm, d);
                float m = (iv && jv) ? d : FLTMAXF;
#pragma unroll
                for (int o = 16; o; o >>= 1) m = fminf(m, __shfl_xor_sync(0xFFFFFFFFu, m, o));
                if (lane == 0 && m < FLTMAXF) atomicMin(&scolb[jj], __float_as_uint(m));
            }
        }
        if (iv) atomicMin(&g_rowmin[nb + gi], __float_as_uint(rowm));
    }
    __syncthreads();
    if (t < 128) {
        int gj = j0 + t;
        if (gj < N && scolb[t] != 0x7F7FFFFFu) atomicMin(&g_colmin[nb + gj], scolb[t]);
    }
    __syncthreads();
    if (wid == 0) T5_DEALLOC(tmem, 128);

#else
    // ================= scalar fallback (round-6 validated logic, 4 x 64x64 subtiles) =================
    const float* Xb = g_X + off + (size_t)b * c * NPAD;
    const float* Yb = g_Y + off + (size_t)b * c * NPAD;
    int tx = t & 15, ty = t >> 4;
    float* As = (float*)smem;                 // [16][64]
    float* Bs = As + 16 * 64;                 // [16][64]
    unsigned* srow = (unsigned*)(Bs + 16 * 64);
    unsigned* scol = srow + 64;
    const float* nX = g_normX + nb;
    const float* nY = g_normY + nb;

    for (int sub = 0; sub < 4; sub++) {
        int i0 = blockIdx.y * 128 + (sub >> 1) * 64;
        int j0 = blockIdx.x * 128 + (sub & 1) * 64;
        float acc[4][4];
#pragma unroll
        for (int i = 0; i < 4; i++)
#pragma unroll
            for (int j = 0; j < 4; j++) acc[i][j] = 0.f;

        for (int k0 = 0; k0 < c; k0 += 16) {
#pragma unroll
            for (int r = 0; r < 4; r++) {
                int id = r * 256 + t;
                int kk = id >> 6, nn = id & 63;
                As[kk * 64 + nn] = Xb[(k0 + kk) * NPAD + i0 + nn];
                Bs[kk * 64 + nn] = Yb[(k0 + kk) * NPAD + j0 + nn];
            }
            __syncthreads();
#pragma unroll
            for (int k = 0; k < 16; k++) {
                float4 a4 = *reinterpret_cast<const float4*>(&As[k * 64 + ty * 4]);
                float4 b4 = *reinterpret_cast<const float4*>(&Bs[k * 64 + tx * 4]);
                float a[4] = {a4.x, a4.y, a4.z, a4.w};
                float bb[4] = {b4.x, b4.y, b4.z, b4.w};
#pragma unroll
                for (int i = 0; i < 4; i++)
#pragma unroll
                    for (int j = 0; j < 4; j++) acc[i][j] += a[i] * bb[j];
            }
            __syncthreads();
        }

        if (t < 64) { srow[t] = 0x7F7FFFFFu; scol[t] = 0x7F7FFFFFu; }
        __syncthreads();
        float nx[4], ny[4];
#pragma unroll
        for (int i = 0; i < 4; i++) {
            nx[i] = nX[i0 + ty * 4 + i] + EPSF;
            ny[i] = nY[j0 + tx * 4 + i] + EPSF;
        }
#pragma unroll
        for (int i = 0; i < 4; i++) {
            int gi = i0 + ty * 4 + i;
#pragma unroll
            for (int j = 0; j < 4; j++) {
                int gj = j0 + tx * 4 + j;
                if (gi < N && gj < N) {
                    float d = 1.0f - acc[i][j] / nx[i] / ny[j];
                    unsigned u = __float_as_uint(d);
                    atomicMin(&srow[ty * 4 + i], u);
                    atomicMin(&scol[tx * 4 + j], u);
                }
            }
        }
        __syncthreads();
        if (t < 64) {
            int gi = i0 + t, gj = j0 + t;
            if (gi < N && srow[t] != 0x7F7FFFFFu) atomicMin(&g_rowmin[nb + gi], srow[t]);
            if (gj < N && scol[t] != 0x7F7FFFFFu) atomicMin(&g_colmin[nb + gj], scol[t]);
        }
        __syncthreads();
    }
#endif
}

// ---------------- split-K fused partial Grams (scalar, validated) ----------------
__global__ void __launch_bounds__(256) covgram_kernel(int c, int off, int lvl) {
    int a0 = blockIdx.y * 64, b0 = blockIdx.x * 64;
    if (a0 > b0) return;
    int b = blockIdx.z & 7, s = blockIdx.z >> 3;
    int kbeg = s * c;
    const float* Xb = g_X + off + (size_t)b * c * NPAD;
    const float* Yb = g_Y + off + (size_t)b * c * NPAD;
    __shared__ float Ax[64][17], Bx[64][17], Ay[64][17], By[64][17];
    int tx = threadIdx.x & 15, ty = threadIdx.x >> 4;
    float accx[4][4], accy[4][4];
#pragma unroll
    for (int i = 0; i < 4; i++)
#pragma unroll
        for (int j = 0; j < 4; j++) { accx[i][j] = 0.f; accy[i][j] = 0.f; }

    int la = threadIdx.x >> 2;
    int lk = (threadIdx.x & 3) * 4;

    for (int k0 = kbeg; k0 < kbeg + c; k0 += 16) {
        float4 v;
        v = *reinterpret_cast<const float4*>(&Xb[(a0 + la) * NPAD + k0 + lk]);
        Ax[la][lk + 0] = v.x; Ax[la][lk + 1] = v.y; Ax[la][lk + 2] = v.z; Ax[la][lk + 3] = v.w;
        v = *reinterpret_cast<const float4*>(&Xb[(b0 + la) * NPAD + k0 + lk]);
        Bx[la][lk + 0] = v.x; Bx[la][lk + 1] = v.y; Bx[la][lk + 2] = v.z; Bx[la][lk + 3] = v.w;
        v = *reinterpret_cast<const float4*>(&Yb[(a0 + la) * NPAD + k0 + lk]);
        Ay[la][lk + 0] = v.x; Ay[la][lk + 1] = v.y; Ay[la][lk + 2] = v.z; Ay[la][lk + 3] = v.w;
        v = *reinterpret_cast<const float4*>(&Yb[(b0 + la) * NPAD + k0 + lk]);
        By[la][lk + 0] = v.x; By[la][lk + 1] = v.y; By[la][lk + 2] = v.z; By[la][lk + 3] = v.w;
        __syncthreads();
#pragma unroll
        for (int k = 0; k < 16; k++) {
            float xa[4], xb[4], ya[4], yb[4];
#pragma unroll
            for (int i = 0; i < 4; i++) {
                xa[i] = Ax[ty * 4 + i][k];
                ya[i] = Ay[ty * 4 + i][k];
                xb[i] = Bx[tx * 4 + i][k];
                yb[i] = By[tx * 4 + i][k];
            }
#pragma unroll
            for (int i = 0; i < 4; i++)
#pragma unroll
                for (int j = 0; j < 4; j++) {
                    accx[i][j] += xa[i] * xb[j];
                    accy[i][j] += ya[i] * yb[j];
                }
        }
        __syncthreads();
    }

    float* px = g_covPX + off + (size_t)(s * 8 + b) * c * c;
    float* py = g_covPY + off + (size_t)(s * 8 + b) * c * c;
#pragma unroll
    for (int i = 0; i < 4; i++) {
        int ga = a0 + ty * 4 + i;
#pragma unroll
        for (int j = 0; j < 4; j++) {
            int gb = b0 + tx * 4 + j;
            px[(size_t)ga * c + gb] = accx[i][j];
            py[(size_t)ga * c + gb] = accy[i][j];
        }
    }
}

// ---------------- sum slices, mean-correct, accumulate w*|covX - covY| ----------------
__global__ void covabs_kernel(int c, int off, int lvl, int N) {
    int b = blockIdx.y;
    int t = blockIdx.x * 256 + threadIdx.x;
    float local = 0.f;
    int ga = t / c, gb = t % c;
    if (ga <= gb) {
        int S = NPAD / c;
        float sx = 0.f, sy = 0.f;
        for (int s = 0; s < S; s++) {
            size_t idx = (size_t)off + (size_t)(s * 8 + b) * c * c + t;
            sx += g_covPX[idx];
            sy += g_covPY[idx];
        }
        const float* mX = g_meanX + (lvl * 8 + b) * 512;
        const float* mY = g_meanY + (lvl * 8 + b) * 512;
        float inv = 1.0f / (float)(N - 1), fN = (float)N;
        float cx = (sx - fN * mX[ga] * mX[gb]) * inv;
        float cy = (sy - fN * mY[ga] * mY[gb]) * inv;
        local = (ga < gb ? 2.f : 1.f) * fabsf(cx - cy);
    }
#pragma unroll
    for (int o = 16; o; o >>= 1) local += __shfl_xor_sync(0xFFFFFFFFu, local, o);
    __shared__ float red[8];
    if ((threadIdx.x & 31) == 0) red[threadIdx.x >> 5] = local;
    __syncthreads();
    if (threadIdx.x == 0) {
        float ssum = 0.f;
        for (int i = 0; i < 8; i++) ssum += red[i];
        atomicAdd(&g_covabs[lvl * 8 + b], ssum);
    }
}

// ---------------- style + mean-abs-diff per (b, level) ----------------
__global__ void stylered_kernel() {
    int b = blockIdx.x, l = blockIdx.y;
    const int cs_[4] = {64, 128, 256, 512};
    const int Ns_[4] = {1000, 1000, 1000, 1024};
    int c = cs_[l], N = Ns_[l];
    int base = (l * 8 + b) * 1024;
    float rs = 0.f, csu = 0.f;
    for (int i = threadIdx.x; i < N; i += 256) {
        rs  += __uint_as_float(g_rowmin[base + i]);
        csu += __uint_as_float(g_colmin[base + i]);
    }
    int mbase = (l * 8 + b) * 512;
    float ms = 0.f;
    for (int ch = threadIdx.x; ch < c; ch += 256)
        ms += fabsf(g_meanX[mbase + ch] - g_meanY[mbase + ch]);

    __shared__ float s1[256], s2[256], s3[256];
    int t = threadIdx.x;
    s1[t] = rs; s2[t] = csu; s3[t] = ms;
    __syncthreads();
    for (int o = 128; o; o >>= 1) {
        if (t < o) { s1[t] += s1[t + o]; s2[t] += s2[t + o]; s3[t] += s3[t + o]; }
        __syncthreads();
    }
    if (t == 0) {
        float style = fmaxf(s1[0] / (float)N, s2[0] / (float)N);
        g_sm[l * 8 + b] = style + s3[0] / (float)c;
    }
}

// ---------------- final scalar ----------------
__global__ void final_kernel(float* __restrict__ out) {
    int t = threadIdx.x;
    const int cs_[4] = {64, 128, 256, 512};
    int l = t >> 3;
    float cc = (float)cs_[l];
    float v = g_sm[t] + g_covabs[t] / (cc * cc);
#pragma unroll
    for (int o = 16; o; o >>= 1) v += __shfl_xor_sync(0xFFFFFFFFu, v, o);
    if (t == 0) out[0] = v * 0.125f;
}

// ---------------- host launcher ----------------
extern "C" void kernel_launch(void* const* d_in, const int* in_sizes, int n_in,
                              void* d_out, int out_size) {
    (void)out_size;
    const float* tgt[4] = {nullptr, nullptr, nullptr, nullptr};
    const float* gen[4] = {nullptr, nullptr, nullptr, nullptr};
    const int* idxp[3]  = {nullptr, nullptr, nullptr};
    int ni = 0;
    for (int i = 0; i < n_in; i++) {
        int lvl = -1;
        switch (in_sizes[i]) {
            case 33554432: lvl = 0; break;
            case 16777216: lvl = 1; break;
            case 8388608:  lvl = 2; break;
            case 4194304:  lvl = 3; break;
            case 8000: if (ni < 3) idxp[ni++] = (const int*)d_in[i]; break;
            default: break;
        }
        if (lvl >= 0) {
            if (!tgt[lvl]) tgt[lvl] = (const float*)d_in[i];
            else           gen[lvl] = (const float*)d_in[i];
        }
    }

    const int cs[4]   = {64, 128, 256, 512};
    const int Ns[4]   = {1000, 1000, 1000, 1024};
    const int hws[4]  = {65536, 16384, 4096, 1024};
    const int offs[4] = {0, 524288, 1572864, 3670016};
    const int GRAM_SMEM = 2048 + 4 * 16384;   // 67584 (fallback needs only ~9KB of it)

    cudaFuncSetAttribute(gram_mma_kernel, cudaFuncAttributeMaxDynamicSharedMemorySize, GRAM_SMEM);

    init_kernel<<<256, 256>>>();
    for (int l = 0; l < 4; l++)
        gather_kernel<<<dim3(cs[l] * 4, 8, 2), 256>>>(
            tgt[l], gen[l], (l < 3) ? idxp[l] : nullptr, cs[l], hws[l], Ns[l], offs[l]);
    for (int l = 0; l < 4; l++)
        bfsplit_kernel<<<dim3(cs[l] / 32, 32, 16), dim3(32, 8)>>>(cs[l], offs[l]);
    for (int l = 0; l < 4; l++) {
        norms_kernel<<<dim3(4, 8, 2), 256>>>(cs[l], offs[l], l);
        means_kernel<<<dim3(cs[l] / 8, 8, 2), 256>>>(cs[l], Ns[l], offs[l], l);
    }
    for (int l = 0; l < 4; l++)
        covgram_kernel<<<dim3(cs[l] / 64, cs[l] / 64, 8 * (NPAD / cs[l])), 256>>>(
            cs[l], offs[l], l);
    for (int l = 0; l < 4; l++)
        gram_mma_kernel<<<dim3(8, 8, 8), 256, GRAM_SMEM>>>(cs[l], Ns[l], offs[l], l);
    for (int l = 0; l < 4; l++)
        covabs_kernel<<<dim3(cs[l] * cs[l] / 256, 8), 256>>>(cs[l], offs[l], l, Ns[l]);
    stylered_kernel<<<dim3(8, 4), 256>>>();
    final_kernel<<<1, 32>>>((float*)d_out);
}

// round 16
// speedup vs baseline: 2.1401x; 1.1113x over previous
#include <cuda_runtime.h>
#include <cuda_bf16.h>
#include <math.h>
#include <stdint.h>

#define EPSF 1e-10f
#define NPAD 1024
#define FLTMAXF 3.402823466e+38f

// ---------------- scratch (device globals; no allocation allowed) ----------------
__device__ float g_X[7864320];   // [level][b][ch][n], n zero-padded to 1024
__device__ float g_Y[7864320];
__device__ __nv_bfloat16 g_XThi[7864320];  // transposed [level][b][n][ch], bf16 hi (for gram)
__device__ __nv_bfloat16 g_XTlo[7864320];
__device__ __nv_bfloat16 g_YThi[7864320];
__device__ __nv_bfloat16 g_YTlo[7864320];
__device__ __nv_bfloat16 g_Xhi[7864320];   // [ch][n] layout, bf16 hi (for cov; K = n)
__device__ __nv_bfloat16 g_Xlo[7864320];
__device__ __nv_bfloat16 g_Yhi[7864320];
__device__ __nv_bfloat16 g_Ylo[7864320];
__device__ float g_normX[4 * 8 * 1024];
__device__ float g_normY[4 * 8 * 1024];
__device__ float g_meanX[4 * 8 * 512];
__device__ float g_meanY[4 * 8 * 512];
__device__ unsigned g_rowmin[4 * 8 * 1024];
__device__ unsigned g_colmin[4 * 8 * 1024];
__device__ float g_covPX[7864320];   // split-K partial Gram slices (S*c == 1024 per level)
__device__ float g_covPY[7864320];
__device__ float g_covabs[32];
__device__ float g_sm[32];

// ---------------- ptx helpers ----------------
__device__ __forceinline__ uint32_t smem_u32(const void* p) {
    uint32_t a;
    asm("{ .reg .u64 t; cvta.to.shared.u64 t, %1; cvt.u32.u64 %0, t; }" : "=r"(a) : "l"(p));
    return a;
}
__device__ __forceinline__ uint32_t elect1() {
    uint32_t p;
    asm volatile("{ .reg .pred p; elect.sync _|p, 0xFFFFFFFF; selp.b32 %0, 1, 0, p; }" : "=r"(p));
    return p;
}
#define SWZ128(x) ((x) ^ (((x) >> 3) & 0x70))
// SW128 K-major desc: layout=2, version=1, SBO=64, LBO=1 (validated in examples + round 14)
#define DESC_BASE ((uint64_t(2) << 61) | (uint64_t(1) << 46) | (uint64_t(64) << 32) | (uint64_t(1) << 16))
#define MK_DESC(a) (DESC_BASE | ((uint64_t)((a) >> 4) & 0x3FFF))

#define MBAR_INIT(mb, n) asm volatile("mbarrier.init.shared.b64 [%0], %1;" :: "r"(mb), "r"(n) : "memory")
#define MBAR_WAIT(mb, ph) do { \
    uint32_t _m = (mb), _p = (ph), _d; \
    asm volatile("{ .reg .pred p; mbarrier.try_wait.parity.acquire.cta.shared::cta.b64 p, [%1], %2; selp.b32 %0, 1, 0, p; }" \
                 : "=r"(_d) : "r"(_m), "r"(_p) : "memory"); \
    if (!_d) { \
        asm volatile("{ .reg .pred P1;\nWL_%=:\n mbarrier.try_wait.parity.acquire.cta.shared::cta.b64 P1, [%0], %1, 0x989680;\n @P1 bra.uni WD_%=;\n bra.uni WL_%=;\nWD_%=:\n}" \
                     :: "r"(_m), "r"(_p) : "memory"); \
    } } while (0)
#define FENCE_ASYNC()    asm volatile("fence.proxy.async.shared::cta;" ::: "memory")

// ---- tcgen05 is sm_103a-only; plain sm_103 pass compiles the scalar fallbacks ----
#if defined(__CUDA_ARCH__) && defined(__CUDA_ARCH_FEAT_SM103_ALL)
#define HAS_TCGEN05 1
#endif

#define T5_ALLOC(sa, n)  asm volatile("tcgen05.alloc.cta_group::1.sync.aligned.shared::cta.b32 [%0], %1;" :: "r"(sa), "r"(n) : "memory")
#define T5_RELINQ()      asm volatile("tcgen05.relinquish_alloc_permit.cta_group::1.sync.aligned;")
#define T5_DEALLOC(t, n) asm volatile("tcgen05.dealloc.cta_group::1.sync.aligned.b32 %0, %1;" :: "r"(t), "r"(n))
#define T5_COMMIT(mb)    asm volatile("tcgen05.commit.cta_group::1.mbarrier::arrive::one.shared::cluster.b64 [%0];" :: "r"(mb) : "memory")
#define T5_FENCE_AFTER() asm volatile("tcgen05.fence::after_thread_sync;" ::: "memory")
#define T5_WAIT_LD()     asm volatile("tcgen05.wait::ld.sync.aligned;" ::: "memory")
#define T5_LD_X32(r, ta) \
    asm volatile("tcgen05.ld.sync.aligned.32x32b.x32.b32 " \
        "{%0,%1,%2,%3,%4,%5,%6,%7,%8,%9,%10,%11,%12,%13,%14,%15," \
        "%16,%17,%18,%19,%20,%21,%22,%23,%24,%25,%26,%27,%28,%29,%30,%31}, [%32];" \
        : "=r"((r)[0]),"=r"((r)[1]),"=r"((r)[2]),"=r"((r)[3]),"=r"((r)[4]),"=r"((r)[5]),"=r"((r)[6]),"=r"((r)[7]), \
          "=r"((r)[8]),"=r"((r)[9]),"=r"((r)[10]),"=r"((r)[11]),"=r"((r)[12]),"=r"((r)[13]),"=r"((r)[14]),"=r"((r)[15]), \
          "=r"((r)[16]),"=r"((r)[17]),"=r"((r)[18]),"=r"((r)[19]),"=r"((r)[20]),"=r"((r)[21]),"=r"((r)[22]),"=r"((r)[23]), \
          "=r"((r)[24]),"=r"((r)[25]),"=r"((r)[26]),"=r"((r)[27]),"=r"((r)[28]),"=r"((r)[29]),"=r"((r)[30]),"=r"((r)[31]) \
        : "r"(ta))

#ifdef HAS_TCGEN05
__device__ __forceinline__ void mma_f16_ss_cg1(uint32_t d, uint64_t a, uint64_t b,
                                               uint32_t idesc, uint32_t en) {
    asm volatile(
        "{\n\t.reg .pred p;\n\tsetp.ne.u32 p, %5, 0;\n\t"
        "tcgen05.mma.cta_group::1.kind::f16 [%0], %1, %2, %3, {%4, %4, %4, %4}, p;\n\t}"
        :: "r"(d), "l"(a), "l"(b), "r"(idesc), "r"(0u), "r"(en) : "memory");
}
#endif

// idesc kind::f16: dtype=F32(1<<4), a=BF16(1<<7), b=BF16(1<<10), N/8<<17, M/16<<24; M=N=128
#define GRAM_IDESC ((1u << 4) | (1u << 7) | (1u << 10) | ((128u / 8) << 17) | ((128u / 16) << 24))

// ---------------- init ----------------
__global__ void init_kernel() {
    int t = blockIdx.x * 256 + threadIdx.x;
    if (t < 4 * 8 * 1024) {
        g_rowmin[t] = 0x7F7FFFFFu;   // FLT_MAX bits; distances > 0 so uint order == float order
        g_colmin[t] = 0x7F7FFFFFu;
    }
    if (t < 32) g_covabs[t] = 0.f;
}

// ---------------- gather ----------------
__global__ void gather_kernel(const float* __restrict__ tgt, const float* __restrict__ gen,
                              const int* __restrict__ idx, int c, int hw, int N, int off) {
    int b = blockIdx.y, tsel = blockIdx.z;
    const float* src = tsel ? gen : tgt;
    float* dst = (tsel ? g_Y : g_X) + off;
    int t = blockIdx.x * 256 + threadIdx.x;
    int ch = t >> 10, n = t & 1023;
    float v = 0.f;
    if (n < N) {
        int pos = idx ? idx[b * N + n] : n;
        v = src[((size_t)b * c + ch) * hw + pos];
    }
    dst[((size_t)b * c + ch) * NPAD + n] = v;
}

// ---------------- bf16 hi/lo split: [ch][n] fp32 -> [n][ch] bf16 x2 AND [ch][n] bf16 x2 ----------------
__global__ void bfsplit_kernel(int c, int off) {
    __shared__ float tile[32][33];
    int b = blockIdx.z & 7, tsel = blockIdx.z >> 3;
    size_t base = (size_t)off + (size_t)b * c * NPAD;
    const float* src = (tsel ? g_Y : g_X) + base;
    __nv_bfloat16* dthi = (tsel ? g_YThi : g_XThi) + base;   // [n][ch]
    __nv_bfloat16* dtlo = (tsel ? g_YTlo : g_XTlo) + base;
    __nv_bfloat16* dhi  = (tsel ? g_Yhi  : g_Xhi)  + base;   // [ch][n]
    __nv_bfloat16* dlo  = (tsel ? g_Ylo  : g_Xlo)  + base;
    int ch0 = blockIdx.x * 32, n0 = blockIdx.y * 32;
#pragma unroll
    for (int r = threadIdx.y; r < 32; r += 8) {
        float v = src[(size_t)(ch0 + r) * NPAD + n0 + threadIdx.x];
        tile[r][threadIdx.x] = v;
        __nv_bfloat16 h = __float2bfloat16(v);
        __nv_bfloat16 l = __float2bfloat16(v - __bfloat162float(h));
        size_t o = (size_t)(ch0 + r) * NPAD + n0 + threadIdx.x;
        dhi[o] = h;
        dlo[o] = l;
    }
    __syncthreads();
#pragma unroll
    for (int r = threadIdx.y; r < 32; r += 8) {
        float v = tile[threadIdx.x][r];
        __nv_bfloat16 h = __float2bfloat16(v);
        __nv_bfloat16 l = __float2bfloat16(v - __bfloat162float(h));
        size_t o = (size_t)(n0 + r) * c + ch0 + threadIdx.x;
        dthi[o] = h;
        dtlo[o] = l;
    }
}

// ---------------- per-point L2 norms ----------------
__global__ void norms_kernel(int c, int off, int lvl) {
    int b = blockIdx.y, tsel = blockIdx.z;
    const float* src = (tsel ? g_Y : g_X) + off + (size_t)b * c * NPAD;
    float* dst = (tsel ? g_normY : g_normX) + (lvl * 8 + b) * 1024;
    int n = blockIdx.x * 256 + threadIdx.x;
    float s = 0.f;
    for (int ch = 0; ch < c; ch++) { float v = src[ch * NPAD + n]; s += v * v; }
    dst[n] = sqrtf(s);
}

// ---------------- per-channel means ----------------
__global__ void means_kernel(int c, int N, int off, int lvl) {
    int b = blockIdx.y, tsel = blockIdx.z;
    const float* src = (tsel ? g_Y : g_X) + off + (size_t)b * c * NPAD;
    float* dst = (tsel ? g_meanY : g_meanX) + (lvl * 8 + b) * 512;
    int ch = blockIdx.x * 8 + (threadIdx.x >> 5);
    int lane = threadIdx.x & 31;
    if (ch >= c) return;
    float s = 0.f;
    for (int n = lane; n < NPAD; n += 32) s += src[ch * NPAD + n];
#pragma unroll
    for (int o = 16; o; o >>= 1) s += __shfl_xor_sync(0xFFFFFFFFu, s, o);
    if (lane == 0) dst[ch] = s / (float)N;
}

// ---------------- Gram + cosine distance + row/col min (validated round-14) ----------------
__global__ void __launch_bounds__(256) gram_mma_kernel(int c, int N, int off, int lvl) {
    extern __shared__ char smem[];
    int t = threadIdx.x;
    int b = blockIdx.z;
    int nb = (lvl * 8 + b) * 1024;

#ifdef HAS_TCGEN05
    uint32_t sb = smem_u32(smem);
    int wid = t >> 5, lane = t & 31;
    int i0 = blockIdx.y * 128, j0 = blockIdx.x * 128;

    if (wid == 0) { T5_ALLOC(sb, 128); T5_RELINQ(); }
    __syncthreads();
    uint32_t tmem;
    asm volatile("ld.shared.b32 %0, [%1];" : "=r"(tmem) : "r"(sb));

    float* sny = (float*)(smem + 16);
    unsigned* scolb = (unsigned*)(smem + 528);
    if (t == 0) MBAR_INIT(sb + 8, 1);
    if (t < 128) {
        sny[t] = g_normY[nb + j0 + t] + EPSF;
        scolb[t] = 0x7F7FFFFFu;
    }
    __syncthreads();

    const __nv_bfloat16* ga[4] = {
        g_XThi + off + ((size_t)b * NPAD + i0) * c,
        g_XTlo + off + ((size_t)b * NPAD + i0) * c,
        g_YThi + off + ((size_t)b * NPAD + j0) * c,
        g_YTlo + off + ((size_t)b * NPAD + j0) * c
    };

    int nchunks = c / 64;
    for (int ck = 0; ck < nchunks; ck++) {
        int kc = ck * 64;
#pragma unroll
        for (int q = 0; q < 4; q++) {
            char* tb = smem + 2048 + q * 16384;
            const __nv_bfloat16* gp = ga[q] + kc;
#pragma unroll
            for (int r = 0; r < 4; r++) {
                int id = r * 256 + t;
                int row = id >> 3, c16 = id & 7;
                uint4 v = *(const uint4*)(gp + (size_t)row * c + c16 * 8);
                uint32_t bo = row * 128 + c16 * 16;
                *(uint4*)(tb + SWZ128(bo)) = v;
            }
        }
        __syncthreads();
        if (wid == 0 && elect1()) {
            FENCE_ASYNC();
            uint64_t dAh = MK_DESC(sb + 2048);
            uint64_t dAl = MK_DESC(sb + 2048 + 16384);
            uint64_t dBh = MK_DESC(sb + 2048 + 32768);
            uint64_t dBl = MK_DESC(sb + 2048 + 49152);
            uint64_t pa[3] = {dAh, dAh, dAl};
            uint64_t pb[3] = {dBh, dBl, dBh};
#pragma unroll
            for (int pi = 0; pi < 3; pi++)
#pragma unroll
                for (int ks = 0; ks < 4; ks++) {
                    uint32_t en = (ck > 0 || pi > 0 || ks > 0) ? 1u : 0u;
                    mma_f16_ss_cg1(tmem, pa[pi] + ks * 2, pb[pi] + ks * 2, GRAM_IDESC, en);
                }
            T5_COMMIT(sb + 8);
        }
        MBAR_WAIT(sb + 8, (uint32_t)(ck & 1));
        __syncthreads();
    }
    T5_FENCE_AFTER();

    if (t < 128) {
        int gi = i0 + wid * 32 + lane;
        bool iv = gi < N;
        float nx = g_normX[nb + gi] + EPSF;
        float rowm = FLTMAXF;
#pragma unroll
        for (int h = 0; h < 2; h++) {
            uint32_t r0[32], r1[32];
            T5_LD_X32(r0, tmem + h * 64);
            T5_LD_X32(r1, tmem + h * 64 + 32);
            T5_WAIT_LD();
#pragma unroll
            for (int j = 0; j < 64; j++) {
                int jj = h * 64 + j;
                int gj = j0 + jj;
                float g = __uint_as_float(j < 32 ? r0[j] : r1[j - 32]);
                float d = 1.0f - g / nx / sny[jj];
                bool jv = gj < N;
                if (jv) rowm = fminf(rowm, d);
                float m = (iv && jv) ? d : FLTMAXF;
#pragma unroll
                for (int o = 16; o; o >>= 1) m = fminf(m, __shfl_xor_sync(0xFFFFFFFFu, m, o));
                if (lane == 0 && m < FLTMAXF) atomicMin(&scolb[jj], __float_as_uint(m));
            }
        }
        if (iv) atomicMin(&g_rowmin[nb + gi], __float_as_uint(rowm));
    }
    __syncthreads();
    if (t < 128) {
        int gj = j0 + t;
        if (gj < N && scolb[t] != 0x7F7FFFFFu) atomicMin(&g_colmin[nb + gj], scolb[t]);
    }
    __syncthreads();
    if (wid == 0) T5_DEALLOC(tmem, 128);

#else
    // scalar fallback (round-6 validated logic over 4 x 64x64 subtiles)
    const float* Xb = g_X + off + (size_t)b * c * NPAD;
    const float* Yb = g_Y + off + (size_t)b * c * NPAD;
    int tx = t & 15, ty = t >> 4;
    float* As = (float*)smem;
    float* Bs = As + 16 * 64;
    unsigned* srow = (unsigned*)(Bs + 16 * 64);
    unsigned* scol = srow + 64;
    const float* nX = g_normX + nb;
    const float* nY = g_normY + nb;

    for (int sub = 0; sub < 4; sub++) {
        int i0 = blockIdx.y * 128 + (sub >> 1) * 64;
        int j0 = blockIdx.x * 128 + (sub & 1) * 64;
        float acc[4][4];
#pragma unroll
        for (int i = 0; i < 4; i++)
#pragma unroll
            for (int j = 0; j < 4; j++) acc[i][j] = 0.f;
        for (int k0 = 0; k0 < c; k0 += 16) {
#pragma unroll
            for (int r = 0; r < 4; r++) {
                int id = r * 256 + t;
                int kk = id >> 6, nn = id & 63;
                As[kk * 64 + nn] = Xb[(k0 + kk) * NPAD + i0 + nn];
                Bs[kk * 64 + nn] = Yb[(k0 + kk) * NPAD + j0 + nn];
            }
            __syncthreads();
#pragma unroll
            for (int k = 0; k < 16; k++) {
                float4 a4 = *reinterpret_cast<const float4*>(&As[k * 64 + ty * 4]);
                float4 b4 = *reinterpret_cast<const float4*>(&Bs[k * 64 + tx * 4]);
                float a[4] = {a4.x, a4.y, a4.z, a4.w};
                float bb[4] = {b4.x, b4.y, b4.z, b4.w};
#pragma unroll
                for (int i = 0; i < 4; i++)
#pragma unroll
                    for (int j = 0; j < 4; j++) acc[i][j] += a[i] * bb[j];
            }
            __syncthreads();
        }
        if (t < 64) { srow[t] = 0x7F7FFFFFu; scol[t] = 0x7F7FFFFFu; }
        __syncthreads();
        float nx[4], ny[4];
#pragma unroll
        for (int i = 0; i < 4; i++) {
            nx[i] = nX[i0 + ty * 4 + i] + EPSF;
            ny[i] = nY[j0 + tx * 4 + i] + EPSF;
        }
#pragma unroll
        for (int i = 0; i < 4; i++) {
            int gi = i0 + ty * 4 + i;
#pragma unroll
            for (int j = 0; j < 4; j++) {
                int gj = j0 + tx * 4 + j;
                if (gi < N && gj < N) {
                    float d = 1.0f - acc[i][j] / nx[i] / ny[j];
                    unsigned u = __float_as_uint(d);
                    atomicMin(&srow[ty * 4 + i], u);
                    atomicMin(&scol[tx * 4 + j], u);
                }
            }
        }
        __syncthreads();
        if (t < 64) {
            int gi = i0 + t, gj = j0 + t;
            if (gi < N && srow[t] != 0x7F7FFFFFu) atomicMin(&g_rowmin[nb + gi], srow[t]);
            if (gj < N && scol[t] != 0x7F7FFFFFu) atomicMin(&g_colmin[nb + gj], scol[t]);
        }
        __syncthreads();
    }
#endif
}

// ---------------- tcgen05 split-K cov Grams: X^T X and Y^T Y, 128x128 channel tiles ----------------
// grid (nt, nt, 8*S); z = s*8+b; slice s covers K rows [s*Kslice, (s+1)*Kslice), Kslice = 1024/S.
// Writes raw partial tiles to g_covPX/g_covPY at (s*8+b)*c*c (masked to <c).
// dyn smem: [0] tmem ptr, [8] mbar, 8 tiles of 16KB at 2048 (XhiA,XloA,YhiA,YloA,XhiB,XloB,YhiB,YloB)
__global__ void __launch_bounds__(256) covgram_mma_kernel(int c, int off, int S) {
    int a0 = blockIdx.y * 128, b0 = blockIdx.x * 128;
    if (a0 > b0) return;
    extern __shared__ char smem[];
    int t = threadIdx.x;
    int b = blockIdx.z & 7, s = blockIdx.z >> 3;
    int Kslice = NPAD / S;
    int kbeg = s * Kslice;
    size_t base = (size_t)off + (size_t)b * c * NPAD;
    float* px = g_covPX + off + (size_t)(s * 8 + b) * c * c;
    float* py = g_covPY + off + (size_t)(s * 8 + b) * c * c;

#ifdef HAS_TCGEN05
    uint32_t sb = smem_u32(smem);
    int wid = t >> 5, lane = t & 31;
    if (wid == 0) { T5_ALLOC(sb, 256); T5_RELINQ(); }
    __syncthreads();
    uint32_t tmem;
    asm volatile("ld.shared.b32 %0, [%1];" : "=r"(tmem) : "r"(sb));
    if (t == 0) MBAR_INIT(sb + 8, 1);
    __syncthreads();

    // tile sources: rows are channels (length-NPAD rows), K-major over n
    const __nv_bfloat16* gsrc[8] = {
        g_Xhi + base + (size_t)a0 * NPAD, g_Xlo + base + (size_t)a0 * NPAD,
        g_Yhi + base + (size_t)a0 * NPAD, g_Ylo + base + (size_t)a0 * NPAD,
        g_Xhi + base + (size_t)b0 * NPAD, g_Xlo + base + (size_t)b0 * NPAD,
        g_Yhi + base + (size_t)b0 * NPAD, g_Ylo + base + (size_t)b0 * NPAD
    };

    int nchunks = Kslice / 64;
    for (int ck = 0; ck < nchunks; ck++) {
        int kc = kbeg + ck * 64;
#pragma unroll
        for (int q = 0; q < 8; q++) {
            char* tb = smem + 2048 + q * 16384;
            const __nv_bfloat16* gp = gsrc[q] + kc;
#pragma unroll
            for (int r = 0; r < 4; r++) {
                int id = r * 256 + t;
                int row = id >> 3, c16 = id & 7;
                uint4 v = *(const uint4*)(gp + (size_t)row * NPAD + c16 * 8);
                uint32_t bo = row * 128 + c16 * 16;
                *(uint4*)(tb + SWZ128(bo)) = v;
            }
        }
        __syncthreads();
        if (wid == 0 && elect1()) {
            FENCE_ASYNC();
            uint64_t dXhA = MK_DESC(sb + 2048);
            uint64_t dXlA = MK_DESC(sb + 2048 + 16384);
            uint64_t dYhA = MK_DESC(sb + 2048 + 2 * 16384);
            uint64_t dYlA = MK_DESC(sb + 2048 + 3 * 16384);
            uint64_t dXhB = MK_DESC(sb + 2048 + 4 * 16384);
            uint64_t dXlB = MK_DESC(sb + 2048 + 5 * 16384);
            uint64_t dYhB = MK_DESC(sb + 2048 + 6 * 16384);
            uint64_t dYlB = MK_DESC(sb + 2048 + 7 * 16384);
            uint64_t pxa[3] = {dXhA, dXhA, dXlA};
            uint64_t pxb[3] = {dXhB, dXlB, dXhB};
            uint64_t pya[3] = {dYhA, dYhA, dYlA};
            uint64_t pyb[3] = {dYhB, dYlB, dYhB};
#pragma unroll
            for (int pi = 0; pi < 3; pi++)
#pragma unroll
                for (int ks = 0; ks < 4; ks++) {
                    uint32_t en = (ck > 0 || pi > 0 || ks > 0) ? 1u : 0u;
                    mma_f16_ss_cg1(tmem,       pxa[pi] + ks * 2, pxb[pi] + ks * 2, GRAM_IDESC, en);
                    mma_f16_ss_cg1(tmem + 128, pya[pi] + ks * 2, pyb[pi] + ks * 2, GRAM_IDESC, en);
                }
            T5_COMMIT(sb + 8);
        }
        MBAR_WAIT(sb + 8, (uint32_t)(ck & 1));
        __syncthreads();
    }
    T5_FENCE_AFTER();

    // epilogue: stream both accumulators out as raw partial sums (masked)
    if (t < 128) {
        int ga = a0 + wid * 32 + lane;
        bool av = ga < c;
#pragma unroll
        for (int acc = 0; acc < 2; acc++) {
            float* dst = acc ? py : px;
            uint32_t tbase = tmem + acc * 128;
#pragma unroll
            for (int cb = 0; cb < 4; cb++) {
                uint32_t r[32];
                T5_LD_X32(r, tbase + cb * 32);
                T5_WAIT_LD();
                if (av) {
                    int gb0 = b0 + cb * 32;
#pragma unroll
                    for (int j = 0; j < 32; j++) {
                        int gb = gb0 + j;
                        if (gb < c) dst[(size_t)ga * c + gb] = __uint_as_float(r[j]);
                    }
                }
            }
        }
    }
    __syncthreads();
    if (wid == 0) T5_DEALLOC(tmem, 256);

#else
    // scalar fallback: 4 x 64x64 subtiles with the round-10 cov loop over [kbeg, kbeg+Kslice)
    int tx = t & 15, ty = t >> 4;
    float (*Ax)[17] = (float(*)[17])smem;
    float (*Bx)[17] = Ax + 64;
    float (*Ay)[17] = Bx + 64;
    float (*By)[17] = Ay + 64;
    const float* Xb = g_X + base;
    const float* Yb = g_Y + base;
    int la = t >> 2, lk = (t & 3) * 4;

    for (int sub = 0; sub < 4; sub++) {
        int sa = a0 + (sub >> 1) * 64, sbo = b0 + (sub & 1) * 64;
        if (sa >= c || sbo >= c) continue;
        float accx[4][4], accy[4][4];
#pragma unroll
        for (int i = 0; i < 4; i++)
#pragma unroll
            for (int j = 0; j < 4; j++) { accx[i][j] = 0.f; accy[i][j] = 0.f; }
        for (int k0 = kbeg; k0 < kbeg + Kslice; k0 += 16) {
            float4 v;
            v = *(const float4*)&Xb[(sa + la) * NPAD + k0 + lk];
            Ax[la][lk] = v.x; Ax[la][lk + 1] = v.y; Ax[la][lk + 2] = v.z; Ax[la][lk + 3] = v.w;
            v = *(const float4*)&Xb[(sbo + la) * NPAD + k0 + lk];
            Bx[la][lk] = v.x; Bx[la][lk + 1] = v.y; Bx[la][lk + 2] = v.z; Bx[la][lk + 3] = v.w;
            v = *(const float4*)&Yb[(sa + la) * NPAD + k0 + lk];
            Ay[la][lk] = v.x; Ay[la][lk + 1] = v.y; Ay[la][lk + 2] = v.z; Ay[la][lk + 3] = v.w;
            v = *(const float4*)&Yb[(sbo + la) * NPAD + k0 + lk];
            By[la][lk] = v.x; By[la][lk + 1] = v.y; By[la][lk + 2] = v.z; By[la][lk + 3] = v.w;
            __syncthreads();
#pragma unroll
            for (int k = 0; k < 16; k++) {
                float xa[4], xb2[4], ya[4], yb2[4];
#pragma unroll
                for (int i = 0; i < 4; i++) {
                    xa[i] = Ax[ty * 4 + i][k]; ya[i] = Ay[ty * 4 + i][k];
                    xb2[i] = Bx[tx * 4 + i][k]; yb2[i] = By[tx * 4 + i][k];
                }
#pragma unroll
                for (int i = 0; i < 4; i++)
#pragma unroll
                    for (int j = 0; j < 4; j++) {
                        accx[i][j] += xa[i] * xb2[j];
                        accy[i][j] += ya[i] * yb2[j];
                    }
            }
            __syncthreads();
        }
#pragma unroll
        for (int i = 0; i < 4; i++) {
            int ga = sa + ty * 4 + i;
#pragma unroll
            for (int j = 0; j < 4; j++) {
                int gb = sbo + tx * 4 + j;
                if (ga < c && gb < c) {
                    px[(size_t)ga * c + gb] = accx[i][j];
                    py[(size_t)ga * c + gb] = accy[i][j];
                }
            }
        }
        __syncthreads();
    }
#endif
}

// ---------------- sum slices, mean-correct, accumulate w*|covX - covY| ----------------
__global__ void covabs_kernel(int c, int off, int lvl, int N, int S) {
    int b = blockIdx.y;
    int t = blockIdx.x * 256 + threadIdx.x;
    float local = 0.f;
    int ga = t / c, gb = t % c;
    if (ga <= gb) {
        float sx = 0.f, sy = 0.f;
        for (int s = 0; s < S; s++) {
            size_t idx = (size_t)off + (size_t)(s * 8 + b) * c * c + t;
            sx += g_covPX[idx];
            sy += g_covPY[idx];
        }
        const float* mX = g_meanX + (lvl * 8 + b) * 512;
        const float* mY = g_meanY + (lvl * 8 + b) * 512;
        float inv = 1.0f / (float)(N - 1), fN = (float)N;
        float cx = (sx - fN * mX[ga] * mX[gb]) * inv;
        float cy = (sy - fN * mY[ga] * mY[gb]) * inv;
        local = (ga < gb ? 2.f : 1.f) * fabsf(cx - cy);
    }
#pragma unroll
    for (int o = 16; o; o >>= 1) local += __shfl_xor_sync(0xFFFFFFFFu, local, o);
    __shared__ float red[8];
    if ((threadIdx.x & 31) == 0) red[threadIdx.x >> 5] = local;
    __syncthreads();
    if (threadIdx.x == 0) {
        float ssum = 0.f;
        for (int i = 0; i < 8; i++) ssum += red[i];
        atomicAdd(&g_covabs[lvl * 8 + b], ssum);
    }
}

// ---------------- style + mean-abs-diff per (b, level) ----------------
__global__ void stylered_kernel() {
    int b = blockIdx.x, l = blockIdx.y;
    const int cs_[4] = {64, 128, 256, 512};
    const int Ns_[4] = {1000, 1000, 1000, 1024};
    int c = cs_[l], N = Ns_[l];
    int base = (l * 8 + b) * 1024;
    float rs = 0.f, csu = 0.f;
    for (int i = threadIdx.x; i < N; i += 256) {
        rs  += __uint_as_float(g_rowmin[base + i]);
        csu += __uint_as_float(g_colmin[base + i]);
    }
    int mbase = (l * 8 + b) * 512;
    float ms = 0.f;
    for (int ch = threadIdx.x; ch < c; ch += 256)
        ms += fabsf(g_meanX[mbase + ch] - g_meanY[mbase + ch]);

    __shared__ float s1[256], s2[256], s3[256];
    int t = threadIdx.x;
    s1[t] = rs; s2[t] = csu; s3[t] = ms;
    __syncthreads();
    for (int o = 128; o; o >>= 1) {
        if (t < o) { s1[t] += s1[t + o]; s2[t] += s2[t + o]; s3[t] += s3[t + o]; }
        __syncthreads();
    }
    if (t == 0) {
        float style = fmaxf(s1[0] / (float)N, s2[0] / (float)N);
        g_sm[l * 8 + b] = style + s3[0] / (float)c;
    }
}

// ---------------- final scalar ----------------
__global__ void final_kernel(float* __restrict__ out) {
    int t = threadIdx.x;
    const int cs_[4] = {64, 128, 256, 512};
    int l = t >> 3;
    float cc = (float)cs_[l];
    float v = g_sm[t] + g_covabs[t] / (cc * cc);
#pragma unroll
    for (int o = 16; o; o >>= 1) v += __shfl_xor_sync(0xFFFFFFFFu, v, o);
    if (t == 0) out[0] = v * 0.125f;
}

// ---------------- host launcher ----------------
extern "C" void kernel_launch(void* const* d_in, const int* in_sizes, int n_in,
                              void* d_out, int out_size) {
    (void)out_size;
    const float* tgt[4] = {nullptr, nullptr, nullptr, nullptr};
    const float* gen[4] = {nullptr, nullptr, nullptr, nullptr};
    const int* idxp[3]  = {nullptr, nullptr, nullptr};
    int ni = 0;
    for (int i = 0; i < n_in; i++) {
        int lvl = -1;
        switch (in_sizes[i]) {
            case 33554432: lvl = 0; break;
            case 16777216: lvl = 1; break;
            case 8388608:  lvl = 2; break;
            case 4194304:  lvl = 3; break;
            case 8000: if (ni < 3) idxp[ni++] = (const int*)d_in[i]; break;
            default: break;
        }
        if (lvl >= 0) {
            if (!tgt[lvl]) tgt[lvl] = (const float*)d_in[i];
            else           gen[lvl] = (const float*)d_in[i];
        }
    }

    const int cs[4]   = {64, 128, 256, 512};
    const int Ns[4]   = {1000, 1000, 1000, 1024};
    const int hws[4]  = {65536, 16384, 4096, 1024};
    const int offs[4] = {0, 524288, 1572864, 3670016};
    const int Ss[4]   = {16, 8, 4, 2};        // S*c = 1024 (fills slice budget exactly)
    const int GRAM_SMEM = 2048 + 4 * 16384;   // 67584
    const int COV_SMEM  = 2048 + 8 * 16384;   // 133120

    cudaFuncSetAttribute(gram_mma_kernel, cudaFuncAttributeMaxDynamicSharedMemorySize, GRAM_SMEM);
    cudaFuncSetAttribute(covgram_mma_kernel, cudaFuncAttributeMaxDynamicSharedMemorySize, COV_SMEM);

    init_kernel<<<256, 256>>>();
    for (int l = 0; l < 4; l++)
        gather_kernel<<<dim3(cs[l] * 4, 8, 2), 256>>>(
            tgt[l], gen[l], (l < 3) ? idxp[l] : nullptr, cs[l], hws[l], Ns[l], offs[l]);
    for (int l = 0; l < 4; l++)
        bfsplit_kernel<<<dim3(cs[l] / 32, 32, 16), dim3(32, 8)>>>(cs[l], offs[l]);
    for (int l = 0; l < 4; l++) {
        norms_kernel<<<dim3(4, 8, 2), 256>>>(cs[l], offs[l], l);
        means_kernel<<<dim3(cs[l] / 8, 8, 2), 256>>>(cs[l], Ns[l], offs[l], l);
    }
    for (int l = 0; l < 4; l++) {
        int nt = (cs[l] + 127) / 128;
        covgram_mma_kernel<<<dim3(nt, nt, 8 * Ss[l]), 256, COV_SMEM>>>(cs[l], offs[l], Ss[l]);
    }
    for (int l = 0; l < 4; l++)
        gram_mma_kernel<<<dim3(8, 8, 8), 256, GRAM_SMEM>>>(cs[l], Ns[l], offs[l], l);
    for (int l = 0; l < 4; l++)
        covabs_kernel<<<dim3(cs[l] * cs[l] / 256, 8), 256>>>(cs[l], offs[l], l, Ns[l], Ss[l]);
    stylered_kernel<<<dim3(8, 4), 256>>>();
    final_kernel<<<1, 32>>>((float*)d_out);
}